// round 13
// baseline (speedup 1.0000x reference)
#include <cuda_runtime.h>
#include <cuda_bf16.h>
#include <cstdint>
#include <math.h>

typedef float4 f4;
typedef __nv_bfloat16 bf16;

// ---------------- scratch (device globals; allocation-free rule) ----------------
__device__ bf16  g_c1h[8192ll * 4096];
__device__ bf16  g_c1l[8192ll * 4096];
__device__ bf16  g_wdh[256ll * 4096];
__device__ bf16  g_wdl[256ll * 4096];
__device__ bf16  g_xdh [8192ll * 256];
__device__ bf16  g_xdl [8192ll * 256];
__device__ float g_S1  [32ll * 1024 * 1024];
__device__ float g_S2  [32ll * 1024 * 1024];
__device__ bf16  g_sh  [32ll * 1024 * 1024];
__device__ bf16  g_sl  [32ll * 1024 * 1024];
__device__ bf16  g_vth [32ll * 64 * 1024];
__device__ bf16  g_vtl [32ll * 64 * 1024];
__device__ bf16  g_q2h [32768ll * 192];
__device__ bf16  g_q2l [32768ll * 192];
__device__ float g_scorep[4 * 32 * 1024];
__device__ int   g_topk [32 * 256];
__device__ int   g_inv  [32 * 1024];
__device__ float g_out1[32ll * 1024 * 64];
__device__ bf16  g_c2h[32768ll * 1024];
__device__ bf16  g_c2l[32768ll * 1024];
__device__ bf16  g_wuph[4ll * 256 * 1024];
__device__ bf16  g_wupl[4ll * 256 * 1024];
__device__ float g_cup [32768ll * 256];
__device__ float g_coarse[8ll * 256 * 64 * 64];
__device__ bf16  g_t2h [32768ll * 64];
__device__ bf16  g_t2l [32768ll * 64];
__device__ float g_out2[32ll * 1024 * 64];
__device__ float g_y1  [8ll * 256 * 64 * 64];
__device__ bf16  g_yth [8ll * 4096 * 256];
__device__ bf16  g_ytl [8ll * 4096 * 256];
__device__ bf16  g_wph [256 * 256];
__device__ bf16  g_wpl [256 * 256];
__device__ bf16  g_wch [192 * 64];
__device__ bf16  g_wcl [192 * 64];
__device__ bf16  g_wth [192 * 64];
__device__ bf16  g_wtl [192 * 64];
__device__ float g_bnsc[256];
__device__ float g_bnoff[256];

// =================== helpers ===================
__device__ __forceinline__ uint32_t smem_u32(const void* p) {
    uint32_t a;
    asm("{ .reg .u64 t; cvta.to.shared.u64 t, %1; cvt.u32.u64 %0, t; }" : "=r"(a) : "l"(p));
    return a;
}
__device__ __forceinline__ void cpasync16(uint32_t s, const void* g) {
    asm volatile("cp.async.cg.shared.global [%0], [%1], 16;" :: "r"(s), "l"(g) : "memory");
}
__device__ __forceinline__ void ldsm4(uint32_t* r, uint32_t addr) {
    asm volatile("ldmatrix.sync.aligned.m8n8.x4.shared.b16 {%0,%1,%2,%3}, [%4];"
                 : "=r"(r[0]), "=r"(r[1]), "=r"(r[2]), "=r"(r[3]) : "r"(addr));
}
#define CP_COMMIT() asm volatile("cp.async.commit_group;" ::: "memory")
#define CP_WAIT1()  asm volatile("cp.async.wait_group 1;" ::: "memory")

#define MMA16816(d, a, b) \
    asm volatile("mma.sync.aligned.m16n8k16.row.col.f32.bf16.bf16.f32 " \
        "{%0,%1,%2,%3}, {%4,%5,%6,%7}, {%8,%9}, {%0,%1,%2,%3};" \
        : "+f"((d)[0]), "+f"((d)[1]), "+f"((d)[2]), "+f"((d)[3]) \
        : "r"((a)[0]), "r"((a)[1]), "r"((a)[2]), "r"((a)[3]), \
          "r"((b)[0]), "r"((b)[1]))

// ---------------- bf16 split helpers ----------------
__device__ __forceinline__ void split_bf(float v, bf16& h, bf16& l) {
    h = __float2bfloat16(v);
    l = __float2bfloat16(v - __bfloat162float(h));
}

// ========= split-bf16 3-term HMMA GEMM: C = (Ah+Al)(Bh+Bl)^T (approx) =========
// batching: offA = (bz/aDiv)*aHi + (bz%aDiv)*aLo ; offB = bz*bStr ; offC = bz*cStr
// Output: fp32 C, OR split bf16 (Ch/Cl) when Ch != nullptr.
// Optional per-N-col bias; optional per-M-row affine (rsc/roff) + relu6 epilogue.
template<int BN>
__global__ void __launch_bounds__(256, 1) gemm_mma(
    const bf16* __restrict__ Ah, const bf16* __restrict__ Al,
    const bf16* __restrict__ Bh, const bf16* __restrict__ Bl,
    float* __restrict__ C, bf16* __restrict__ Ch, bf16* __restrict__ Cl,
    const float* __restrict__ bias,
    const float* __restrict__ rsc, const float* __restrict__ roff,
    int K, int lda, int ldb, int ldc,
    int aDiv, long long aHi, long long aLo, long long bStr, long long cStr)
{
    constexpr int WM = (BN == 128) ? 4 : 2;
    constexpr int RS = 80;
    constexpr int ASZ = 128 * RS;
    constexpr int BSZ = BN * RS;
    constexpr int STG = 2 * ASZ + 2 * BSZ;

    extern __shared__ char smraw[];
    uint32_t sb = smem_u32(smraw);

    const int tid = threadIdx.x;
    const int wid = tid >> 5, lane = tid & 31;
    long long bz = blockIdx.z;
    long long aOff = (bz / aDiv) * aHi + (bz % aDiv) * aLo;
    Ah += aOff; Al += aOff;
    Bh += bz * bStr; Bl += bz * bStr;
    if (C) C += bz * cStr;
    if (Ch) { Ch += bz * cStr; Cl += bz * cStr; }
    const int m0 = blockIdx.y * 128, n0 = blockIdx.x * BN;

    const int wm0 = (BN == 128) ? (wid & 1) * 64 : (wid & 3) * 32;
    const int wn0 = (BN == 128) ? (wid >> 1) * 32 : (wid >> 2) * 32;

    float acc[WM][4][4];
#pragma unroll
    for (int i = 0; i < WM; i++)
#pragma unroll
        for (int j = 0; j < 4; j++)
#pragma unroll
            for (int k = 0; k < 4; k++) acc[i][j][k] = 0.f;

    const int T = K >> 5;

    auto fill = [&](int t) {
        int k0 = t << 5;
        uint32_t st = sb + (t & 1) * STG;
#pragma unroll
        for (int half = 0; half < 2; half++) {
            int idx = tid + half * 256;
            int r = idx >> 2, q = idx & 3;
            long long go = (long long)(m0 + r) * lda + k0 + q * 8;
            uint32_t sA = st + r * RS + q * 16;
            cpasync16(sA, Ah + go);
            cpasync16(sA + ASZ, Al + go);
        }
#pragma unroll
        for (int half = 0; half < BN / 64; half++) {
            int idx = tid + half * 256;
            int r = idx >> 2, q = idx & 3;
            long long go = (long long)(n0 + r) * ldb + k0 + q * 8;
            uint32_t sB = st + 2 * ASZ + r * RS + q * 16;
            cpasync16(sB, Bh + go);
            cpasync16(sB + BSZ, Bl + go);
        }
    };

    fill(0); CP_COMMIT();
    fill(1); CP_COMMIT();

    const uint32_t aPat = (((lane >> 3) & 1) * 8 + (lane & 7)) * RS + (lane >> 4) * 16;
    const uint32_t bPat = (((lane >> 4) & 1) * 8 + (lane & 7)) * RS + ((lane >> 3) & 1) * 16;

    for (int t = 0; t < T; t++) {
        CP_WAIT1();
        __syncthreads();
        uint32_t st = sb + (t & 1) * STG;
#pragma unroll
        for (int ks = 0; ks < 2; ks++) {
            uint32_t ah[WM][4], alr[WM][4];
            uint32_t aoff = st + wm0 * RS + ks * 32 + aPat;
#pragma unroll
            for (int mt = 0; mt < WM; mt++) {
                ldsm4(ah[mt],  aoff + mt * 16 * RS);
                ldsm4(alr[mt], aoff + mt * 16 * RS + ASZ);
            }
            uint32_t bh[4][2], blr[4][2];
            uint32_t boff = st + 2 * ASZ + wn0 * RS + ks * 32 + bPat;
            {
                uint32_t tb[4];
                ldsm4(tb, boff);
                bh[0][0] = tb[0]; bh[0][1] = tb[1]; bh[1][0] = tb[2]; bh[1][1] = tb[3];
                ldsm4(tb, boff + 16 * RS);
                bh[2][0] = tb[0]; bh[2][1] = tb[1]; bh[3][0] = tb[2]; bh[3][1] = tb[3];
                ldsm4(tb, boff + BSZ);
                blr[0][0] = tb[0]; blr[0][1] = tb[1]; blr[1][0] = tb[2]; blr[1][1] = tb[3];
                ldsm4(tb, boff + BSZ + 16 * RS);
                blr[2][0] = tb[0]; blr[2][1] = tb[1]; blr[3][0] = tb[2]; blr[3][1] = tb[3];
            }
#pragma unroll
            for (int term = 0; term < 3; term++)
#pragma unroll
                for (int mt = 0; mt < WM; mt++)
#pragma unroll
                    for (int nt = 0; nt < 4; nt++)
                        MMA16816(acc[mt][nt],
                                 (term == 2) ? alr[mt] : ah[mt],
                                 (term == 1) ? blr[nt] : bh[nt]);
        }
        __syncthreads();
        if (t + 2 < T) fill(t + 2);
        CP_COMMIT();
    }

#pragma unroll
    for (int mt = 0; mt < WM; mt++) {
        int r = wm0 + mt * 16 + (lane >> 2);
        float s0 = 1.f, o0 = 0.f, s1 = 1.f, o1 = 0.f;
        bool rowaff = (rsc != nullptr);
        if (rowaff) {
            s0 = rsc[m0 + r]; o0 = roff[m0 + r];
            s1 = rsc[m0 + r + 8]; o1 = roff[m0 + r + 8];
        }
#pragma unroll
        for (int nt = 0; nt < 4; nt++) {
            int c = wn0 + nt * 8 + (lane & 3) * 2;
            float b0 = 0.f, b1 = 0.f;
            if (bias) { b0 = bias[n0 + c]; b1 = bias[n0 + c + 1]; }
            float2 v0, v1;
            if (rowaff) {
                v0.x = fminf(fmaxf(acc[mt][nt][0] * s0 + o0, 0.f), 6.f);
                v0.y = fminf(fmaxf(acc[mt][nt][1] * s0 + o0, 0.f), 6.f);
                v1.x = fminf(fmaxf(acc[mt][nt][2] * s1 + o1, 0.f), 6.f);
                v1.y = fminf(fmaxf(acc[mt][nt][3] * s1 + o1, 0.f), 6.f);
            } else {
                v0.x = acc[mt][nt][0] + b0; v0.y = acc[mt][nt][1] + b1;
                v1.x = acc[mt][nt][2] + b0; v1.y = acc[mt][nt][3] + b1;
            }
            long long o0i = (long long)(m0 + r) * ldc + n0 + c;
            long long o1i = (long long)(m0 + r + 8) * ldc + n0 + c;
            if (Ch) {
                bf16 h, l;
                __nv_bfloat162 hh, ll;
                split_bf(v0.x, h, l); hh.x = h; ll.x = l;
                split_bf(v0.y, h, l); hh.y = h; ll.y = l;
                *(__nv_bfloat162*)(Ch + o0i) = hh;
                *(__nv_bfloat162*)(Cl + o0i) = ll;
                split_bf(v1.x, h, l); hh.x = h; ll.x = l;
                split_bf(v1.y, h, l); hh.y = h; ll.y = l;
                *(__nv_bfloat162*)(Ch + o1i) = hh;
                *(__nv_bfloat162*)(Cl + o1i) = ll;
            } else {
                *(float2*)(C + o0i) = v0;
                *(float2*)(C + o1i) = v1;
            }
        }
    }
}

// im2col for down conv (4x4, stride2, pad1), smem-tiled.
__global__ void __launch_bounds__(256) im2col1_kernel(const float* __restrict__ x) {
    __shared__ float tile[32 * 257];
    int oh = blockIdx.x, cg = blockIdx.y, b = blockIdx.z;
    int tid = threadIdx.x;
#pragma unroll
    for (int idx = tid; idx < 32 * 256; idx += 256) {
        int ic = idx >> 8, rw = idx & 255;
        int r = rw >> 6, iw = rw & 63;
        int ih = 2 * oh - 1 + r;
        float v = 0.f;
        if ((unsigned)ih < 64u)
            v = x[(((long long)(b * 256 + cg * 32 + ic)) << 12) + ih * 64 + iw];
        tile[ic * 257 + rw] = v;
    }
    __syncthreads();
    int ow = tid >> 3, sub = tid & 7;
    int iw0 = 2 * ow - 1;
    long long orow = ((long long)(b * 1024 + oh * 32 + ow)) * 4096 + (cg * 32 + sub * 4) * 16;
#pragma unroll
    for (int j = 0; j < 4; j++) {
        const float* tp = &tile[(sub * 4 + j) * 257];
        bf16 hb[16], lb[16];
#pragma unroll
        for (int kh = 0; kh < 4; kh++) {
#pragma unroll
            for (int kw = 0; kw < 4; kw++) {
                int iw = iw0 + kw;
                float v = ((unsigned)iw < 64u) ? tp[kh * 64 + iw] : 0.f;
                split_bf(v, hb[kh * 4 + kw], lb[kh * 4 + kw]);
            }
        }
        *(uint4*)(g_c1h + orow + j * 16) = *(uint4*)hb;
        *(uint4*)(g_c1h + orow + j * 16 + 8) = *(uint4*)(hb + 8);
        *(uint4*)(g_c1l + orow + j * 16) = *(uint4*)lb;
        *(uint4*)(g_c1l + orow + j * 16 + 8) = *(uint4*)(lb + 8);
    }
}

// split down_w [256 x 4096]
__global__ void split_wd(const float* __restrict__ w) {
    int i = blockIdx.x * 256 + threadIdx.x;
    if (i >= 256 * 4096) return;
    bf16 h, l; split_bf(w[i], h, l);
    g_wdh[i] = h; g_wdl[i] = l;
}

// generic fp32 -> split bf16 (weights only)
__global__ void splitarr(const float* __restrict__ src, bf16* __restrict__ h,
                         bf16* __restrict__ l, long long n) {
    long long i = (long long)blockIdx.x * 256 + threadIdx.x;
    if (i >= n) return;
    bf16 hh, ll; split_bf(src[i], hh, ll);
    h[i] = hh; l[i] = ll;
}

// BN2 constants
__global__ void bn_prep(const float* __restrict__ g2, const float* __restrict__ b2,
                        const float* __restrict__ m2, const float* __restrict__ v2) {
    int i = threadIdx.x;
    float sc = g2[i] / sqrtf(v2[i] + 1e-5f);
    g_bnsc[i] = sc;
    g_bnoff[i] = b2[i] - m2[i] * sc;
}

// V^T relayout from split qkv: vth[bn][d][tok] = q2h[(bn*1024+tok)*192 + 128 + d]
__global__ void vsplit_t() {
    __shared__ uint16_t th[32][72], tl[32][72];
    int bn = blockIdx.y, tk0 = blockIdx.x * 32;
    int tid = threadIdx.x;
#pragma unroll
    for (int idx = tid; idx < 32 * 64; idx += 256) {
        int tok = idx >> 6, d = idx & 63;
        size_t src = ((size_t)bn * 1024 + tk0 + tok) * 192 + 128 + d;
        th[tok][d] = ((const uint16_t*)g_q2h)[src];
        tl[tok][d] = ((const uint16_t*)g_q2l)[src];
    }
    __syncthreads();
#pragma unroll
    for (int idx = tid; idx < 32 * 64; idx += 256) {
        int d = idx >> 5, tok = idx & 31;
        size_t o = ((size_t)bn * 64 + d) * 1024 + tk0 + tok;
        ((uint16_t*)g_vth)[o] = th[tok][d];
        ((uint16_t*)g_vtl)[o] = tl[tok][d];
    }
}

// ---------------- softmax over 1024-wide rows -> split bf16 probs ----------------
__global__ void softmax_rows2(const float* __restrict__ S, bf16* __restrict__ Sh, bf16* __restrict__ Sl) {
    size_t row = blockIdx.x;
    const float4* rp = reinterpret_cast<const float4*>(S + (row << 10));
    int t = threadIdx.x;
    float4 v = rp[t];
    float mx = fmaxf(fmaxf(v.x, v.y), fmaxf(v.z, v.w));
    __shared__ float red[8];
#pragma unroll
    for (int o = 16; o > 0; o >>= 1) mx = fmaxf(mx, __shfl_xor_sync(0xffffffffu, mx, o));
    if ((t & 31) == 0) red[t >> 5] = mx;
    __syncthreads();
    mx = red[0];
#pragma unroll
    for (int i = 1; i < 8; i++) mx = fmaxf(mx, red[i]);
    v.x = expf(v.x - mx); v.y = expf(v.y - mx); v.z = expf(v.z - mx); v.w = expf(v.w - mx);
    float sm = v.x + v.y + v.z + v.w;
#pragma unroll
    for (int o = 16; o > 0; o >>= 1) sm += __shfl_xor_sync(0xffffffffu, sm, o);
    __syncthreads();
    if ((t & 31) == 0) red[t >> 5] = sm;
    __syncthreads();
    sm = red[0];
#pragma unroll
    for (int i = 1; i < 8; i++) sm += red[i];
    float inv = 1.0f / sm;
    v.x *= inv; v.y *= inv; v.z *= inv; v.w *= inv;
    size_t o = (row << 10) + (size_t)t * 4;
    bf16 h0, l0, h1, l1, h2, l2, h3, l3;
    split_bf(v.x, h0, l0); split_bf(v.y, h1, l1);
    split_bf(v.z, h2, l2); split_bf(v.w, h3, l3);
    __nv_bfloat162 ph0; ph0.x = h0; ph0.y = h1;
    __nv_bfloat162 ph1; ph1.x = h2; ph1.y = h3;
    __nv_bfloat162 pl0; pl0.x = l0; pl0.y = l1;
    __nv_bfloat162 pl1; pl1.x = l2; pl1.y = l3;
    *(__nv_bfloat162*)(Sh + o) = ph0;
    *(__nv_bfloat162*)(Sh + o + 2) = ph1;
    *(__nv_bfloat162*)(Sl + o) = pl0;
    *(__nv_bfloat162*)(Sl + o + 2) = pl1;
}

// colsum partials: 4 columns/thread, vectorized bf16x4 loads, 4 row-chunks
__global__ void colsum_part() {
    int idx = blockIdx.x * 256 + threadIdx.x;
    int bn = idx >> 8, j4 = (idx & 255) * 4;
    int ic = blockIdx.y;
    const bf16* bh = g_sh + ((size_t)bn << 20) + j4;
    const bf16* bl = g_sl + ((size_t)bn << 20) + j4;
    float s0 = 0.f, s1 = 0.f, s2 = 0.f, s3 = 0.f;
    for (int i = ic * 256; i < ic * 256 + 256; i++) {
        uint2 vh = *(const uint2*)(bh + ((size_t)i << 10));
        uint2 vl = *(const uint2*)(bl + ((size_t)i << 10));
        __nv_bfloat162 h01 = *(__nv_bfloat162*)&vh.x;
        __nv_bfloat162 h23 = *(__nv_bfloat162*)&vh.y;
        __nv_bfloat162 l01 = *(__nv_bfloat162*)&vl.x;
        __nv_bfloat162 l23 = *(__nv_bfloat162*)&vl.y;
        s0 += __bfloat162float(h01.x) + __bfloat162float(l01.x);
        s1 += __bfloat162float(h01.y) + __bfloat162float(l01.y);
        s2 += __bfloat162float(h23.x) + __bfloat162float(l23.x);
        s3 += __bfloat162float(h23.y) + __bfloat162float(l23.y);
    }
    f4 r; r.x = s0; r.y = s1; r.z = s2; r.w = s3;
    *(f4*)(g_scorep + ((size_t)ic * 32768 + bn * 1024 + j4)) = r;
}

// bitonic full sort of 1024 (score,idx) pairs descending (jax tie-break: lower idx first)
// loads = sum of 4 colsum partials (score_reduce folded in)
__global__ void __launch_bounds__(512) topk_kernel() {
    int bn = blockIdx.x, tid = threadIdx.x;
    __shared__ float sv[1024];
    __shared__ int   si[1024];
    for (int i = tid; i < 1024; i += 512) {
        float s = 0.f;
#pragma unroll
        for (int ic = 0; ic < 4; ic++) s += g_scorep[(size_t)ic * 32768 + bn * 1024 + i];
        sv[i] = s; si[i] = i;
    }
    __syncthreads();
    for (int k = 2; k <= 1024; k <<= 1) {
        for (int j = k >> 1; j > 0; j >>= 1) {
            for (int i = tid; i < 1024; i += 512) {
                int ixj = i ^ j;
                if (ixj > i) {
                    float va = sv[i], vb = sv[ixj];
                    int ia = si[i], ib = si[ixj];
                    bool aFirst = (va > vb) || (va == vb && ia < ib);
                    bool descSeg = ((i & k) == 0);
                    if (descSeg ? !aFirst : aFirst) { sv[i] = vb; sv[ixj] = va; si[i] = ib; si[ixj] = ia; }
                }
            }
            __syncthreads();
        }
    }
    for (int i = tid; i < 1024; i += 512) g_inv[bn * 1024 + i] = -1;
    __syncthreads();
    for (int kk = tid; kk < 256; kk += 512) {
        int id = si[kk];
        g_topk[bn * 256 + kk] = id;
        g_inv[bn * 1024 + id] = kk;
    }
}

// permuted up-conv weights (bf16 hi/lo): wup[p][cout][cin*4+t]
__global__ void build_wup(const float* __restrict__ up_w) {
    int i = blockIdx.x * 256 + threadIdx.x;
    if (i >= 4 * 256 * 1024) return;
    int t = i & 3, cin = (i >> 2) & 255, cout = (i >> 10) & 255, p = i >> 18;
    int kh = (1 - (p >> 1)) + 2 * (t >> 1);
    int kw = (1 - (p & 1)) + 2 * (t & 1);
    float v = up_w[(((long long)cin * 256 + cout) * 4 + kh) * 4 + kw];
    bf16 h, l; split_bf(v, h, l);
    g_wuph[i] = h; g_wupl[i] = l;
}

// im2col for conv-transpose: thread per (row, cin) -> 4 contiguous elems
__global__ void im2col2_kernel() {
    int i = blockIdx.x * 256 + threadIdx.x;
    if (i >= 32768 * 256) return;
    int cin = i & 255, row = i >> 8;
    int n = cin >> 6, d = cin & 63;
    int p = row >> 13, r = row & 8191;
    int b = r >> 10, q = r & 1023, qh = q >> 5, qw = q & 31;
    int oh = qh * 2 + (p >> 1), ow = qw * 2 + (p & 1);
    bf16 hb[4], lb[4];
#pragma unroll
    for (int t = 0; t < 4; t++) {
        int dh = t >> 1, dw = t & 1;
        int ih = ((oh + 1) >> 1) - dh, iw = ((ow + 1) >> 1) - dw;
        float v = 0.f;
        if ((unsigned)ih < 32u && (unsigned)iw < 32u)
            v = g_out1[((size_t)(b * 4 + n) * 1024 + ih * 32 + iw) * 64 + d];
        split_bf(v, hb[t], lb[t]);
    }
    long long o = (long long)row * 1024 + cin * 4;
    *(uint2*)(g_c2h + o) = *(uint2*)hb;
    *(uint2*)(g_c2l + o) = *(uint2*)lb;
}

// coarse_out[b][c][oh][ow] = cup[p][b*1024 + (oh/2)*32 + ow/2][c] + up_b[c]  (tiled transpose)
__global__ void remap_coarse(const float* __restrict__ up_b) {
    __shared__ float t[64][33];
    int b = blockIdx.z, c0 = blockIdx.y * 32, oh = blockIdx.x;
    int tid = threadIdx.x;
    int poh = (oh & 1) * 2;
    int rbase = b * 1024 + (oh >> 1) * 32;
#pragma unroll
    for (int idx = tid; idx < 64 * 32; idx += 256) {
        int ow = idx >> 5, cc = idx & 31;
        int p = poh + (ow & 1);
        t[ow][cc] = g_cup[((size_t)(p * 8192 + rbase + (ow >> 1))) * 256 + c0 + cc] + up_b[c0 + cc];
    }
    __syncthreads();
#pragma unroll
    for (int idx = tid; idx < 64 * 32; idx += 256) {
        int cc = idx >> 6, ow = idx & 63;
        g_coarse[((size_t)(b * 256 + c0 + cc)) * 4096 + oh * 64 + ow] = t[ow][cc];
    }
}

// gather top-k patch tokens directly from pixel-major g_cup -> split bf16 tokens
__global__ void gather_tokens(const float* __restrict__ up_b) {
    int i = blockIdx.x * 256 + threadIdx.x;
    if (i >= 32768 * 64) return;
    int d = i & 63, row = i >> 6;
    int j = row & 1023, bn = row >> 10, b = bn >> 2, n = bn & 3;
    int k = j >> 2, rr = (j >> 1) & 1, cc = j & 1;
    int pidx = g_topk[bn * 256 + k];
    int c = n * 64 + d;
    float v = g_cup[((size_t)((rr * 2 + cc) * 8192 + b * 1024 + pidx)) * 256 + c] + up_b[c];
    bf16 h, l; split_bf(v, h, l);
    g_t2h[i] = h; g_t2l[i] = l;
}

// y1 = coarse_out + region
__global__ void final_add() {
    int i = blockIdx.x * 256 + threadIdx.x;
    if (i >= 8 * 256 * 4096) return;
    int s = i & 4095, c = (i >> 12) & 255, b = i >> 20;
    int oh = s >> 6, ow = s & 63;
    int p = s >> 2, rr = (s >> 1) & 1, cc = s & 1;
    int sh = 2 * (p >> 5) + rr, sw = 2 * (p & 31) + cc;
    size_t cbase = (size_t)(b * 256 + c) * 4096;
    float v = g_coarse[cbase + oh * 64 + ow] + g_coarse[cbase + sh * 64 + sw];
    int n = c >> 6, d = c & 63, bn = b * 4 + n;
    int k = g_inv[bn * 1024 + p];
    if (k >= 0) v += g_out2[((size_t)bn * 1024 + (k * 4 + rr * 2 + cc)) * 64 + d];
    g_y1[i] = v;
}

// fused: depthwise 3x3 + BN + relu6 + transpose + split -> g_yth/g_ytl [b][s][c]
__global__ void __launch_bounds__(256) dwconv_fused(
    const float* __restrict__ dw_w,
    const float* __restrict__ g1, const float* __restrict__ b1,
    const float* __restrict__ m1, const float* __restrict__ v1)
{
    __shared__ float tile[32 * 193];
    __shared__ float ot[64][33];
    int oh = blockIdx.x, cg = blockIdx.y, b = blockIdx.z;
    int tid = threadIdx.x;
#pragma unroll
    for (int idx = tid; idx < 32 * 192; idx += 256) {
        int c = idx / 192, rw = idx % 192;
        int r = rw >> 6, iw = rw & 63;
        int ih = oh - 1 + r;
        float v = 0.f;
        if ((unsigned)ih < 64u)
            v = g_y1[(((size_t)(b * 256 + cg * 32 + c)) << 12) + ih * 64 + iw];
        tile[c * 193 + rw] = v;
    }
    __syncthreads();
    int c = tid & 31, og = tid >> 5;
    int gc = cg * 32 + c;
    float w[9];
#pragma unroll
    for (int k = 0; k < 9; k++) w[k] = dw_w[gc * 9 + k];
    float sc = g1[gc] / sqrtf(v1[gc] + 1e-5f);
    float off = b1[gc] - m1[gc] * sc;
    bool topEdge = (oh == 0), botEdge = (oh == 63);
    const float* tp = &tile[c * 193];
#pragma unroll
    for (int j = 0; j < 8; j++) {
        int ow = og * 8 + j;
        float acc = 0.f;
#pragma unroll
        for (int kh = 0; kh < 3; kh++) {
            if ((kh == 0 && topEdge) || (kh == 2 && botEdge)) continue;
#pragma unroll
            for (int kw = 0; kw < 3; kw++) {
                int iw = ow + kw - 1;
                if ((unsigned)iw < 64u)
                    acc += w[kh * 3 + kw] * tp[kh * 64 + iw];
            }
        }
        float val = fminf(fmaxf(acc * sc + off, 0.f), 6.f);
        ot[ow][c] = val;
    }
    __syncthreads();
#pragma unroll
    for (int idx = tid; idx < 64 * 32; idx += 256) {
        int ow = idx >> 5, c2 = idx & 31;
        float v = ot[ow][c2];
        bf16 h, l; split_bf(v, h, l);
        size_t o = ((size_t)(b * 4096 + oh * 64 + ow)) * 256 + cg * 32 + c2;
        g_yth[o] = h; g_ytl[o] = l;
    }
}

// ---------------- launch ----------------
extern "C" void kernel_launch(void* const* d_in, const int* in_sizes, int n_in,
                              void* d_out, int out_size) {
    const float* x      = (const float*)d_in[0];
    const float* down_w = (const float*)d_in[1];
    const float* down_b = (const float*)d_in[2];
    const float* up_w   = (const float*)d_in[3];
    const float* up_b   = (const float*)d_in[4];
    const float* cqkv_w = (const float*)d_in[5];
    const float* cqkv_b = (const float*)d_in[6];
    const float* tqkv_w = (const float*)d_in[7];
    const float* tqkv_b = (const float*)d_in[8];
    const float* dw_w   = (const float*)d_in[9];
    const float* bn1_g  = (const float*)d_in[10];
    const float* bn1_b  = (const float*)d_in[11];
    const float* bn1_m  = (const float*)d_in[12];
    const float* bn1_v  = (const float*)d_in[13];
    const float* pw_w   = (const float*)d_in[14];
    const float* bn2_g  = (const float*)d_in[15];
    const float* bn2_b  = (const float*)d_in[16];
    const float* bn2_m  = (const float*)d_in[17];
    const float* bn2_v  = (const float*)d_in[18];
    float* out = (float*)d_out;

    bf16 *c1h, *c1l, *wdh, *wdl, *c2h, *c2l, *wuph, *wupl, *sh, *sl, *vth, *vtl, *q2h, *q2l;
    bf16 *yth, *ytl, *wph, *wpl, *xdh, *xdl, *t2h, *t2l, *wch, *wcl, *wth, *wtl;
    float *S1, *S2, *out1, *cup, *out2, *bnsc, *bnoff;
    cudaGetSymbolAddress((void**)&c1h,  g_c1h);
    cudaGetSymbolAddress((void**)&c1l,  g_c1l);
    cudaGetSymbolAddress((void**)&wdh,  g_wdh);
    cudaGetSymbolAddress((void**)&wdl,  g_wdl);
    cudaGetSymbolAddress((void**)&xdh,  g_xdh);
    cudaGetSymbolAddress((void**)&xdl,  g_xdl);
    cudaGetSymbolAddress((void**)&S1,   g_S1);
    cudaGetSymbolAddress((void**)&S2,   g_S2);
    cudaGetSymbolAddress((void**)&sh,   g_sh);
    cudaGetSymbolAddress((void**)&sl,   g_sl);
    cudaGetSymbolAddress((void**)&vth,  g_vth);
    cudaGetSymbolAddress((void**)&vtl,  g_vtl);
    cudaGetSymbolAddress((void**)&q2h,  g_q2h);
    cudaGetSymbolAddress((void**)&q2l,  g_q2l);
    cudaGetSymbolAddress((void**)&out1, g_out1);
    cudaGetSymbolAddress((void**)&c2h,  g_c2h);
    cudaGetSymbolAddress((void**)&c2l,  g_c2l);
    cudaGetSymbolAddress((void**)&wuph, g_wuph);
    cudaGetSymbolAddress((void**)&wupl, g_wupl);
    cudaGetSymbolAddress((void**)&cup,  g_cup);
    cudaGetSymbolAddress((void**)&t2h,  g_t2h);
    cudaGetSymbolAddress((void**)&t2l,  g_t2l);
    cudaGetSymbolAddress((void**)&out2, g_out2);
    cudaGetSymbolAddress((void**)&yth,  g_yth);
    cudaGetSymbolAddress((void**)&ytl,  g_ytl);
    cudaGetSymbolAddress((void**)&wph,  g_wph);
    cudaGetSymbolAddress((void**)&wpl,  g_wpl);
    cudaGetSymbolAddress((void**)&wch,  g_wch);
    cudaGetSymbolAddress((void**)&wcl,  g_wcl);
    cudaGetSymbolAddress((void**)&wth,  g_wth);
    cudaGetSymbolAddress((void**)&wtl,  g_wtl);
    cudaGetSymbolAddress((void**)&bnsc, g_bnsc);
    cudaGetSymbolAddress((void**)&bnoff, g_bnoff);

    cudaFuncSetAttribute(gemm_mma<128>, cudaFuncAttributeMaxDynamicSharedMemorySize, 81920);
    cudaFuncSetAttribute(gemm_mma<64>,  cudaFuncAttributeMaxDynamicSharedMemorySize, 61440);

    dim3 blk(256);

    // weight prep
    build_wup<<<(4 * 256 * 1024 + 255) / 256, blk>>>(up_w);
    split_wd<<<(256 * 4096 + 255) / 256, blk>>>(down_w);
    splitarr<<<(256 * 256 + 255) / 256, blk>>>(pw_w, wph, wpl, 256 * 256);
    splitarr<<<(192 * 64 + 255) / 256, blk>>>(cqkv_w, wch, wcl, 192 * 64);
    splitarr<<<(192 * 64 + 255) / 256, blk>>>(tqkv_w, wth, wtl, 192 * 64);
    bn_prep<<<1, 256>>>(bn2_g, bn2_b, bn2_m, bn2_v);

    // 1) down conv: smem-tiled im2col(bf16 split) + HMMA GEMM + bias, split-bf16 out
    im2col1_kernel<<<dim3(32, 8, 8), blk>>>(x);
    gemm_mma<128><<<dim3(2, 64, 1), blk, 81920>>>(c1h, c1l, wdh, wdl,
        nullptr, xdh, xdl, down_b, nullptr, nullptr,
        4096, 4096, 4096, 256, 1, 0, 0, 0, 0);

    // 2) coarse QKV (HMMA, batched over b,n; split-bf16 out into q2h/q2l)
    gemm_mma<64><<<dim3(3, 8, 32), blk, 61440>>>(xdh, xdl, wch, wcl,
        nullptr, q2h, q2l, cqkv_b, nullptr, nullptr,
        64, 256, 64, 192, 4, 1024ll * 256, 64, 0, 1024ll * 192);

    // 3) S1 = K @ Q^T (HMMA); softmax->split; colsum; topk (reduce folded in)
    gemm_mma<128><<<dim3(8, 8, 32), blk, 81920>>>(q2h + 64, q2l + 64, q2h, q2l,
        S1, nullptr, nullptr, nullptr, nullptr, nullptr,
        64, 192, 192, 1024, 1, 1024ll * 192, 0, 1024ll * 192, 1ll << 20);
    softmax_rows2<<<32768, blk>>>(S1, sh, sl);
    colsum_part<<<dim3(32, 4), blk>>>();
    topk_kernel<<<32, 512>>>();

    // 4) out1 = attn @ V (HMMA on split probs; V^T relayout from split qkv)
    vsplit_t<<<dim3(32, 32), blk>>>();
    gemm_mma<64><<<dim3(1, 8, 32), blk, 61440>>>(sh, sl, vth, vtl,
        out1, nullptr, nullptr, nullptr, nullptr, nullptr,
        1024, 1024, 1024, 64, 1, 1ll << 20, 0, 64ll * 1024, 1024ll * 64);

    // 5) up conv (transposed): parity im2col + HMMA GEMM + remap
    im2col2_kernel<<<32768, blk>>>();
    gemm_mma<128><<<dim3(2, 64, 4), blk, 81920>>>(c2h, c2l, wuph, wupl,
        cup, nullptr, nullptr, nullptr, nullptr, nullptr,
        1024, 1024, 1024, 256, 1, 8192ll * 1024, 0, 256ll * 1024, 8192ll * 256);
    remap_coarse<<<dim3(64, 8, 8), blk>>>(up_b);

    // 6) top-k token gather (split out) + QKV2 (HMMA, split out)
    gather_tokens<<<(32768 * 64 + 255) / 256, blk>>>(up_b);
    gemm_mma<64><<<dim3(3, 256, 1), blk, 61440>>>(t2h, t2l, wth, wtl,
        nullptr, q2h, q2l, tqkv_b, nullptr, nullptr,
        64, 64, 64, 192, 1, 0, 0, 0, 0);

    // 7) S2 (HMMA); softmax->split; out2 (HMMA)
    gemm_mma<128><<<dim3(8, 8, 32), blk, 81920>>>(q2h + 64, q2l + 64, q2h, q2l,
        S2, nullptr, nullptr, nullptr, nullptr, nullptr,
        64, 192, 192, 1024, 1, 1024ll * 192, 0, 1024ll * 192, 1ll << 20);
    softmax_rows2<<<32768, blk>>>(S2, sh, sl);
    vsplit_t<<<dim3(32, 32), blk>>>();
    gemm_mma<64><<<dim3(1, 8, 32), blk, 61440>>>(sh, sl, vth, vtl,
        out2, nullptr, nullptr, nullptr, nullptr, nullptr,
        1024, 1024, 1024, 64, 1, 1ll << 20, 0, 64ll * 1024, 1024ll * 64);

    // 8) residual + scatter-add; fused dwconv+BN+relu6+transpose+split
    final_add<<<(8 * 256 * 4096 + 255) / 256, blk>>>();
    dwconv_fused<<<dim3(64, 8, 8), blk>>>(dw_w, bn1_g, bn1_b, bn1_m, bn1_v);

    // 9) PW 1x1 conv transposed (A=W, B=Y^T) + fused BN2+relu6, writes d_out directly
    gemm_mma<128><<<dim3(32, 2, 8), blk, 81920>>>(wph, wpl, yth, ytl,
        out, nullptr, nullptr, nullptr, bnsc, bnoff,
        256, 256, 256, 4096, 1, 0, 0, 4096ll * 256, 256ll * 4096);
}

// round 15
// speedup vs baseline: 1.0208x; 1.0208x over previous
#include <cuda_runtime.h>
#include <cuda_bf16.h>
#include <cstdint>
#include <math.h>

typedef float4 f4;
typedef __nv_bfloat16 bf16;

// ---------------- scratch (device globals; allocation-free rule) ----------------
__device__ bf16  g_c1h[8192ll * 4096];
__device__ bf16  g_c1l[8192ll * 4096];
__device__ bf16  g_wdh[256ll * 4096];
__device__ bf16  g_wdl[256ll * 4096];
__device__ float g_xd  [8192ll * 256];
__device__ bf16  g_xdh [8192ll * 256];
__device__ bf16  g_xdl [8192ll * 256];
__device__ float g_qkv1[32768ll * 192];
__device__ float g_S1  [32ll * 1024 * 1024];
__device__ float g_S2  [32ll * 1024 * 1024];
__device__ bf16  g_vth [32ll * 64 * 1024];
__device__ bf16  g_vtl [32ll * 64 * 1024];
__device__ bf16  g_q2h [32768ll * 192];
__device__ bf16  g_q2l [32768ll * 192];
__device__ float g_stat[32768 * 2];
__device__ float g_scorep[8 * 32 * 1024];
__device__ int   g_topk [32 * 256];
__device__ int   g_inv  [32 * 1024];
__device__ float g_out1[32ll * 1024 * 64];
__device__ bf16  g_c2h[32768ll * 1024];
__device__ bf16  g_c2l[32768ll * 1024];
__device__ bf16  g_wuph[4ll * 256 * 1024];
__device__ bf16  g_wupl[4ll * 256 * 1024];
__device__ float g_cup [32768ll * 256];
__device__ float g_coarse[8ll * 256 * 64 * 64];
__device__ bf16  g_t2h [32768ll * 64];
__device__ bf16  g_t2l [32768ll * 64];
__device__ float g_qkv2[32768ll * 192];
__device__ float g_out2[32ll * 1024 * 64];
__device__ float g_y1  [8ll * 256 * 64 * 64];
__device__ bf16  g_yth [8ll * 4096 * 256];
__device__ bf16  g_ytl [8ll * 4096 * 256];
__device__ bf16  g_wph [256 * 256];
__device__ bf16  g_wpl [256 * 256];
__device__ bf16  g_wch [192 * 64];
__device__ bf16  g_wcl [192 * 64];
__device__ bf16  g_wth [192 * 64];
__device__ bf16  g_wtl [192 * 64];
__device__ float g_bnsc[256];
__device__ float g_bnoff[256];

// =================== helpers ===================
__device__ __forceinline__ uint32_t smem_u32(const void* p) {
    uint32_t a;
    asm("{ .reg .u64 t; cvta.to.shared.u64 t, %1; cvt.u32.u64 %0, t; }" : "=r"(a) : "l"(p));
    return a;
}
__device__ __forceinline__ void cpasync16(uint32_t s, const void* g) {
    asm volatile("cp.async.cg.shared.global [%0], [%1], 16;" :: "r"(s), "l"(g) : "memory");
}
__device__ __forceinline__ void ldsm4(uint32_t* r, uint32_t addr) {
    asm volatile("ldmatrix.sync.aligned.m8n8.x4.shared.b16 {%0,%1,%2,%3}, [%4];"
                 : "=r"(r[0]), "=r"(r[1]), "=r"(r[2]), "=r"(r[3]) : "r"(addr));
}
__device__ __forceinline__ void sts64(uint32_t addr, uint32_t a, uint32_t b) {
    asm volatile("st.shared.v2.b32 [%0], {%1, %2};" :: "r"(addr), "r"(a), "r"(b) : "memory");
}
#define CP_COMMIT() asm volatile("cp.async.commit_group;" ::: "memory")
#define CP_WAIT1()  asm volatile("cp.async.wait_group 1;" ::: "memory")
#define CP_WAIT0()  asm volatile("cp.async.wait_group 0;" ::: "memory")

#define MMA16816(d, a, b) \
    asm volatile("mma.sync.aligned.m16n8k16.row.col.f32.bf16.bf16.f32 " \
        "{%0,%1,%2,%3}, {%4,%5,%6,%7}, {%8,%9}, {%0,%1,%2,%3};" \
        : "+f"((d)[0]), "+f"((d)[1]), "+f"((d)[2]), "+f"((d)[3]) \
        : "r"((a)[0]), "r"((a)[1]), "r"((a)[2]), "r"((a)[3]), \
          "r"((b)[0]), "r"((b)[1]))

// ---------------- bf16 split helpers ----------------
__device__ __forceinline__ void split_bf(float v, bf16& h, bf16& l) {
    h = __float2bfloat16(v);
    l = __float2bfloat16(v - __bfloat162float(h));
}
__device__ __forceinline__ uint32_t pack2(bf16 a, bf16 b) {
    return ((uint32_t)__bfloat16_as_ushort(b) << 16) | __bfloat16_as_ushort(a);
}

// ========= split-bf16 3-term HMMA GEMM: C = (Ah+Al)(Bh+Bl)^T (approx) =========
template<int BN>
__global__ void __launch_bounds__(256, 1) gemm_mma(
    const bf16* __restrict__ Ah, const bf16* __restrict__ Al,
    const bf16* __restrict__ Bh, const bf16* __restrict__ Bl,
    float* __restrict__ C, const float* __restrict__ bias,
    const float* __restrict__ rsc, const float* __restrict__ roff,
    int K, int lda, int ldb, int ldc,
    int aDiv, long long aHi, long long aLo, long long bStr, long long cStr)
{
    constexpr int WM = (BN == 128) ? 4 : 2;
    constexpr int RS = 80;
    constexpr int ASZ = 128 * RS;
    constexpr int BSZ = BN * RS;
    constexpr int STG = 2 * ASZ + 2 * BSZ;

    extern __shared__ char smraw[];
    uint32_t sb = smem_u32(smraw);

    const int tid = threadIdx.x;
    const int wid = tid >> 5, lane = tid & 31;
    long long bz = blockIdx.z;
    long long aOff = (bz / aDiv) * aHi + (bz % aDiv) * aLo;
    Ah += aOff; Al += aOff;
    Bh += bz * bStr; Bl += bz * bStr;
    C += bz * cStr;
    const int m0 = blockIdx.y * 128, n0 = blockIdx.x * BN;

    const int wm0 = (BN == 128) ? (wid & 1) * 64 : (wid & 3) * 32;
    const int wn0 = (BN == 128) ? (wid >> 1) * 32 : (wid >> 2) * 32;

    float acc[WM][4][4];
#pragma unroll
    for (int i = 0; i < WM; i++)
#pragma unroll
        for (int j = 0; j < 4; j++)
#pragma unroll
            for (int k = 0; k < 4; k++) acc[i][j][k] = 0.f;

    const int T = K >> 5;

    auto fill = [&](int t) {
        int k0 = t << 5;
        uint32_t st = sb + (t & 1) * STG;
#pragma unroll
        for (int half = 0; half < 2; half++) {
            int idx = tid + half * 256;
            int r = idx >> 2, q = idx & 3;
            long long go = (long long)(m0 + r) * lda + k0 + q * 8;
            uint32_t sA = st + r * RS + q * 16;
            cpasync16(sA, Ah + go);
            cpasync16(sA + ASZ, Al + go);
        }
#pragma unroll
        for (int half = 0; half < BN / 64; half++) {
            int idx = tid + half * 256;
            int r = idx >> 2, q = idx & 3;
            long long go = (long long)(n0 + r) * ldb + k0 + q * 8;
            uint32_t sB = st + 2 * ASZ + r * RS + q * 16;
            cpasync16(sB, Bh + go);
            cpasync16(sB + BSZ, Bl + go);
        }
    };

    fill(0); CP_COMMIT();
    fill(1); CP_COMMIT();

    const uint32_t aPat = (((lane >> 3) & 1) * 8 + (lane & 7)) * RS + (lane >> 4) * 16;
    const uint32_t bPat = (((lane >> 4) & 1) * 8 + (lane & 7)) * RS + ((lane >> 3) & 1) * 16;

    for (int t = 0; t < T; t++) {
        CP_WAIT1();
        __syncthreads();
        uint32_t st = sb + (t & 1) * STG;
#pragma unroll
        for (int ks = 0; ks < 2; ks++) {
            uint32_t ah[WM][4], alr[WM][4];
            uint32_t aoff = st + wm0 * RS + ks * 32 + aPat;
#pragma unroll
            for (int mt = 0; mt < WM; mt++) {
                ldsm4(ah[mt],  aoff + mt * 16 * RS);
                ldsm4(alr[mt], aoff + mt * 16 * RS + ASZ);
            }
            uint32_t bh[4][2], blr[4][2];
            uint32_t boff = st + 2 * ASZ + wn0 * RS + ks * 32 + bPat;
            {
                uint32_t tb[4];
                ldsm4(tb, boff);
                bh[0][0] = tb[0]; bh[0][1] = tb[1]; bh[1][0] = tb[2]; bh[1][1] = tb[3];
                ldsm4(tb, boff + 16 * RS);
                bh[2][0] = tb[0]; bh[2][1] = tb[1]; bh[3][0] = tb[2]; bh[3][1] = tb[3];
                ldsm4(tb, boff + BSZ);
                blr[0][0] = tb[0]; blr[0][1] = tb[1]; blr[1][0] = tb[2]; blr[1][1] = tb[3];
                ldsm4(tb, boff + BSZ + 16 * RS);
                blr[2][0] = tb[0]; blr[2][1] = tb[1]; blr[3][0] = tb[2]; blr[3][1] = tb[3];
            }
#pragma unroll
            for (int term = 0; term < 3; term++)
#pragma unroll
                for (int mt = 0; mt < WM; mt++)
#pragma unroll
                    for (int nt = 0; nt < 4; nt++)
                        MMA16816(acc[mt][nt],
                                 (term == 2) ? alr[mt] : ah[mt],
                                 (term == 1) ? blr[nt] : bh[nt]);
        }
        __syncthreads();
        if (t + 2 < T) fill(t + 2);
        CP_COMMIT();
    }

#pragma unroll
    for (int mt = 0; mt < WM; mt++) {
        int r = wm0 + mt * 16 + (lane >> 2);
        float s0 = 1.f, o0 = 0.f, s1 = 1.f, o1 = 0.f;
        bool rowaff = (rsc != nullptr);
        if (rowaff) {
            s0 = rsc[m0 + r]; o0 = roff[m0 + r];
            s1 = rsc[m0 + r + 8]; o1 = roff[m0 + r + 8];
        }
#pragma unroll
        for (int nt = 0; nt < 4; nt++) {
            int c = wn0 + nt * 8 + (lane & 3) * 2;
            float b0 = 0.f, b1 = 0.f;
            if (bias) { b0 = bias[n0 + c]; b1 = bias[n0 + c + 1]; }
            float2 v0, v1;
            if (rowaff) {
                v0.x = fminf(fmaxf(acc[mt][nt][0] * s0 + o0, 0.f), 6.f);
                v0.y = fminf(fmaxf(acc[mt][nt][1] * s0 + o0, 0.f), 6.f);
                v1.x = fminf(fmaxf(acc[mt][nt][2] * s1 + o1, 0.f), 6.f);
                v1.y = fminf(fmaxf(acc[mt][nt][3] * s1 + o1, 0.f), 6.f);
            } else {
                v0.x = acc[mt][nt][0] + b0; v0.y = acc[mt][nt][1] + b1;
                v1.x = acc[mt][nt][2] + b0; v1.y = acc[mt][nt][3] + b1;
            }
            *(float2*)(C + (long long)(m0 + r) * ldc + n0 + c) = v0;
            *(float2*)(C + (long long)(m0 + r + 8) * ldc + n0 + c) = v1;
        }
    }
}

// ========= fused softmax + colsum(reg) + P@V (probs never touch HBM) =========
// grid (8 iblocks, 32 bn), 256 threads. S row-major [1024x1024]/bn (fp32).
// Vth/Vtl: [bn][64 d][1024 tok]. out: fp32 [bn*1024+i][64].
template<bool COLSUM>
__global__ void __launch_bounds__(256, 1) fused_pv(
    const float* __restrict__ S, const bf16* __restrict__ Vth, const bf16* __restrict__ Vtl,
    float* __restrict__ outp)
{
    constexpr int RS = 80;
    constexpr int PSUB = 128 * RS;      // 10240 (32 toks per sub-tile, 64B data/row)
    constexpr int PSZ = 4 * PSUB;       // 40960
    constexpr int VSUB = 64 * RS;       // 5120
    constexpr int VSZ = 4 * VSUB;       // 20480
    extern __shared__ char smraw[];
    uint32_t sb = smem_u32(smraw);
    uint32_t Ph = sb, Pl = sb + PSZ;
    uint32_t Vb = sb + 2 * PSZ;                       // 2 buffers x (Vh|Vl)
    float* csred = (float*)(smraw + 2 * PSZ + 4 * VSZ);

    const int tid = threadIdx.x, wid = tid >> 5, lane = tid & 31;
    const int bn = blockIdx.y, i0 = blockIdx.x * 128;
    S   += ((size_t)bn << 20) + (size_t)i0 * 1024;
    Vth += (size_t)bn * 65536;
    Vtl += (size_t)bn * 65536;
    outp += ((size_t)bn * 1024 + i0) * 64;
    const float* st2 = g_stat + ((size_t)(bn * 1024 + i0)) * 2;

    auto loadV = [&](int jc) {
        uint32_t vh = Vb + (jc & 1) * (2 * VSZ);
        uint32_t vl = vh + VSZ;
#pragma unroll
        for (int q = 0; q < 4; q++) {
            int idx = tid + q * 256;
            int sc = idx >> 8, rem = idx & 255;
            int d = rem >> 2, seg = rem & 3;
            size_t src = (size_t)d * 1024 + jc * 128 + sc * 32 + seg * 8;
            uint32_t dst = sc * VSUB + d * RS + seg * 16;
            cpasync16(vh + dst, Vth + src);
            cpasync16(vl + dst, Vtl + src);
        }
    };

    float acc[8][4];
#pragma unroll
    for (int i = 0; i < 8; i++)
#pragma unroll
        for (int j = 0; j < 4; j++) acc[i][j] = 0.f;

    const uint32_t aPat = (((lane >> 3) & 1) * 8 + (lane & 7)) * RS + (lane >> 4) * 16;
    const uint32_t bPat = (((lane >> 4) & 1) * 8 + (lane & 7)) * RS + ((lane >> 3) & 1) * 16;
    const int psc = lane >> 3, ppos = lane & 7;

    loadV(0); CP_COMMIT();

    for (int jc = 0; jc < 8; jc++) {
        // phase A: probs -> smem P tiles (RS=80 gemm format), colsum in regs
        float cs0 = 0.f, cs1 = 0.f, cs2 = 0.f, cs3 = 0.f;
#pragma unroll
        for (int rr = 0; rr < 16; rr++) {
            int row = wid * 16 + rr;
            float m = st2[row * 2], iz = st2[row * 2 + 1];
            f4 v = *(const f4*)(S + (size_t)row * 1024 + jc * 128 + lane * 4);
            float p0 = expf(v.x - m) * iz;
            float p1 = expf(v.y - m) * iz;
            float p2 = expf(v.z - m) * iz;
            float p3 = expf(v.w - m) * iz;
            if (COLSUM) { cs0 += p0; cs1 += p1; cs2 += p2; cs3 += p3; }
            bf16 h0, l0, h1, l1, h2, l2, h3, l3;
            split_bf(p0, h0, l0); split_bf(p1, h1, l1);
            split_bf(p2, h2, l2); split_bf(p3, h3, l3);
            uint32_t off = psc * PSUB + row * RS + ppos * 8;
            sts64(Ph + off, pack2(h0, h1), pack2(h2, h3));
            sts64(Pl + off, pack2(l0, l1), pack2(l2, l3));
        }
        if (COLSUM) {
            f4 c4; c4.x = cs0; c4.y = cs1; c4.z = cs2; c4.w = cs3;
            *(f4*)(csred + wid * 128 + lane * 4) = c4;
        }
        CP_WAIT0();
        __syncthreads();
        if (COLSUM && tid < 128) {
            float s = 0.f;
#pragma unroll
            for (int w = 0; w < 8; w++) s += csred[w * 128 + tid];
            g_scorep[((size_t)blockIdx.x * 32 + bn) * 1024 + jc * 128 + tid] = s;
        }
        if (jc + 1 < 8) { loadV(jc + 1); CP_COMMIT(); }
        // phase B: out += P @ V^T  (8 k-steps of 16 toks: sub-tile = ks>>1, half = ks&1)
        uint32_t vh = Vb + (jc & 1) * (2 * VSZ), vl = vh + VSZ;
#pragma unroll
        for (int ks = 0; ks < 8; ks++) {
            uint32_t pbase = Ph + (ks >> 1) * PSUB + (ks & 1) * 32 + wid * 16 * RS + aPat;
            uint32_t ah[4], al[4];
            ldsm4(ah, pbase);
            ldsm4(al, pbase + PSZ);
            uint32_t vbase = (ks >> 1) * VSUB + (ks & 1) * 32;
            uint32_t bh[8][2], bl[8][2];
#pragma unroll
            for (int n2 = 0; n2 < 4; n2++) {
                uint32_t tb[4];
                ldsm4(tb, vh + vbase + n2 * 16 * RS + bPat);
                bh[2 * n2][0] = tb[0]; bh[2 * n2][1] = tb[1];
                bh[2 * n2 + 1][0] = tb[2]; bh[2 * n2 + 1][1] = tb[3];
                ldsm4(tb, vl + vbase + n2 * 16 * RS + bPat);
                bl[2 * n2][0] = tb[0]; bl[2 * n2][1] = tb[1];
                bl[2 * n2 + 1][0] = tb[2]; bl[2 * n2 + 1][1] = tb[3];
            }
#pragma unroll
            for (int term = 0; term < 3; term++)
#pragma unroll
                for (int nt = 0; nt < 8; nt++)
                    MMA16816(acc[nt],
                             (term == 2) ? al : ah,
                             (term == 1) ? bl[nt] : bh[nt]);
        }
        __syncthreads();
    }

    int r = wid * 16 + (lane >> 2);
#pragma unroll
    for (int nt = 0; nt < 8; nt++) {
        int c = nt * 8 + (lane & 3) * 2;
        float2 v0; v0.x = acc[nt][0]; v0.y = acc[nt][1];
        float2 v1; v1.x = acc[nt][2]; v1.y = acc[nt][3];
        *(float2*)(outp + (size_t)r * 64 + c) = v0;
        *(float2*)(outp + (size_t)(r + 8) * 64 + c) = v1;
    }
}

// per-row softmax stats: m, 1/Z
__global__ void softmax_stats(const float* __restrict__ S) {
    size_t row = blockIdx.x;
    const f4* rp = (const f4*)(S + (row << 10));
    int t = threadIdx.x;
    f4 v = rp[t];
    float mx = fmaxf(fmaxf(v.x, v.y), fmaxf(v.z, v.w));
    __shared__ float red[8];
#pragma unroll
    for (int o = 16; o > 0; o >>= 1) mx = fmaxf(mx, __shfl_xor_sync(0xffffffffu, mx, o));
    if ((t & 31) == 0) red[t >> 5] = mx;
    __syncthreads();
    mx = red[0];
#pragma unroll
    for (int i = 1; i < 8; i++) mx = fmaxf(mx, red[i]);
    float sm = expf(v.x - mx) + expf(v.y - mx) + expf(v.z - mx) + expf(v.w - mx);
#pragma unroll
    for (int o = 16; o > 0; o >>= 1) sm += __shfl_xor_sync(0xffffffffu, sm, o);
    __syncthreads();
    if ((t & 31) == 0) red[t >> 5] = sm;
    __syncthreads();
    sm = red[0];
#pragma unroll
    for (int i = 1; i < 8; i++) sm += red[i];
    if (t == 0) {
        g_stat[row * 2] = mx;
        g_stat[row * 2 + 1] = 1.0f / sm;
    }
}

// im2col for down conv (4x4, stride2, pad1), smem-tiled.
__global__ void __launch_bounds__(256) im2col1_kernel(const float* __restrict__ x) {
    __shared__ float tile[32 * 257];
    int oh = blockIdx.x, cg = blockIdx.y, b = blockIdx.z;
    int tid = threadIdx.x;
#pragma unroll
    for (int idx = tid; idx < 32 * 256; idx += 256) {
        int ic = idx >> 8, rw = idx & 255;
        int r = rw >> 6, iw = rw & 63;
        int ih = 2 * oh - 1 + r;
        float v = 0.f;
        if ((unsigned)ih < 64u)
            v = x[(((long long)(b * 256 + cg * 32 + ic)) << 12) + ih * 64 + iw];
        tile[ic * 257 + rw] = v;
    }
    __syncthreads();
    int ow = tid >> 3, sub = tid & 7;
    int iw0 = 2 * ow - 1;
    long long orow = ((long long)(b * 1024 + oh * 32 + ow)) * 4096 + (cg * 32 + sub * 4) * 16;
#pragma unroll
    for (int j = 0; j < 4; j++) {
        const float* tp = &tile[(sub * 4 + j) * 257];
        bf16 hb[16], lb[16];
#pragma unroll
        for (int kh = 0; kh < 4; kh++) {
#pragma unroll
            for (int kw = 0; kw < 4; kw++) {
                int iw = iw0 + kw;
                float v = ((unsigned)iw < 64u) ? tp[kh * 64 + iw] : 0.f;
                split_bf(v, hb[kh * 4 + kw], lb[kh * 4 + kw]);
            }
        }
        *(uint4*)(g_c1h + orow + j * 16) = *(uint4*)hb;
        *(uint4*)(g_c1h + orow + j * 16 + 8) = *(uint4*)(hb + 8);
        *(uint4*)(g_c1l + orow + j * 16) = *(uint4*)lb;
        *(uint4*)(g_c1l + orow + j * 16 + 8) = *(uint4*)(lb + 8);
    }
}

// split down_w [256 x 4096]
__global__ void split_wd(const float* __restrict__ w) {
    int i = blockIdx.x * 256 + threadIdx.x;
    if (i >= 256 * 4096) return;
    bf16 h, l; split_bf(w[i], h, l);
    g_wdh[i] = h; g_wdl[i] = l;
}

// generic fp32 -> split bf16
__global__ void splitarr(const float* __restrict__ src, bf16* __restrict__ h,
                         bf16* __restrict__ l, long long n) {
    long long i = (long long)blockIdx.x * 256 + threadIdx.x;
    if (i >= n) return;
    bf16 hh, ll; split_bf(src[i], hh, ll);
    h[i] = hh; l[i] = ll;
}

// BN2 constants
__global__ void bn_prep(const float* __restrict__ g2, const float* __restrict__ b2,
                        const float* __restrict__ m2, const float* __restrict__ v2) {
    int i = threadIdx.x;
    float sc = g2[i] / sqrtf(v2[i] + 1e-5f);
    g_bnsc[i] = sc;
    g_bnoff[i] = b2[i] - m2[i] * sc;
}

// V^T split (tiled transpose): vth[bn][d][tok] = split(qkv[bn*1024+tok][128+d])
__global__ void vsplit_t(const float* __restrict__ qkv) {
    __shared__ float t[32][65];
    int bn = blockIdx.y, tk0 = blockIdx.x * 32;
    int tid = threadIdx.x;
#pragma unroll
    for (int idx = tid; idx < 32 * 64; idx += 256) {
        int tok = idx >> 6, d = idx & 63;
        t[tok][d] = qkv[((size_t)bn * 1024 + tk0 + tok) * 192 + 128 + d];
    }
    __syncthreads();
#pragma unroll
    for (int idx = tid; idx < 32 * 64; idx += 256) {
        int d = idx >> 5, tok = idx & 31;
        bf16 h, l; split_bf(t[tok][d], h, l);
        size_t o = ((size_t)bn * 64 + d) * 1024 + tk0 + tok;
        g_vth[o] = h; g_vtl[o] = l;
    }
}

// bitonic full sort of 1024 (score,idx) pairs descending (jax tie-break: lower idx first)
// loads = sum of 8 fused_pv colsum partials
__global__ void __launch_bounds__(512) topk_kernel() {
    int bn = blockIdx.x, tid = threadIdx.x;
    __shared__ float sv[1024];
    __shared__ int   si[1024];
    for (int i = tid; i < 1024; i += 512) {
        float s = 0.f;
#pragma unroll
        for (int ic = 0; ic < 8; ic++) s += g_scorep[((size_t)ic * 32 + bn) * 1024 + i];
        sv[i] = s; si[i] = i;
    }
    __syncthreads();
    for (int k = 2; k <= 1024; k <<= 1) {
        for (int j = k >> 1; j > 0; j >>= 1) {
            for (int i = tid; i < 1024; i += 512) {
                int ixj = i ^ j;
                if (ixj > i) {
                    float va = sv[i], vb = sv[ixj];
                    int ia = si[i], ib = si[ixj];
                    bool aFirst = (va > vb) || (va == vb && ia < ib);
                    bool descSeg = ((i & k) == 0);
                    if (descSeg ? !aFirst : aFirst) { sv[i] = vb; sv[ixj] = va; si[i] = ib; si[ixj] = ia; }
                }
            }
            __syncthreads();
        }
    }
    for (int i = tid; i < 1024; i += 512) g_inv[bn * 1024 + i] = -1;
    __syncthreads();
    for (int kk = tid; kk < 256; kk += 512) {
        int id = si[kk];
        g_topk[bn * 256 + kk] = id;
        g_inv[bn * 1024 + id] = kk;
    }
}

// permuted up-conv weights (bf16 hi/lo): wup[p][cout][cin*4+t]
__global__ void build_wup(const float* __restrict__ up_w) {
    int i = blockIdx.x * 256 + threadIdx.x;
    if (i >= 4 * 256 * 1024) return;
    int t = i & 3, cin = (i >> 2) & 255, cout = (i >> 10) & 255, p = i >> 18;
    int kh = (1 - (p >> 1)) + 2 * (t >> 1);
    int kw = (1 - (p & 1)) + 2 * (t & 1);
    float v = up_w[(((long long)cin * 256 + cout) * 4 + kh) * 4 + kw];
    bf16 h, l; split_bf(v, h, l);
    g_wuph[i] = h; g_wupl[i] = l;
}

// im2col for conv-transpose: thread per (row, cin) -> 4 contiguous elems
__global__ void im2col2_kernel() {
    int i = blockIdx.x * 256 + threadIdx.x;
    if (i >= 32768 * 256) return;
    int cin = i & 255, row = i >> 8;
    int n = cin >> 6, d = cin & 63;
    int p = row >> 13, r = row & 8191;
    int b = r >> 10, q = r & 1023, qh = q >> 5, qw = q & 31;
    int oh = qh * 2 + (p >> 1), ow = qw * 2 + (p & 1);
    bf16 hb[4], lb[4];
#pragma unroll
    for (int t = 0; t < 4; t++) {
        int dh = t >> 1, dw = t & 1;
        int ih = ((oh + 1) >> 1) - dh, iw = ((ow + 1) >> 1) - dw;
        float v = 0.f;
        if ((unsigned)ih < 32u && (unsigned)iw < 32u)
            v = g_out1[((size_t)(b * 4 + n) * 1024 + ih * 32 + iw) * 64 + d];
        split_bf(v, hb[t], lb[t]);
    }
    long long o = (long long)row * 1024 + cin * 4;
    *(uint2*)(g_c2h + o) = *(uint2*)hb;
    *(uint2*)(g_c2l + o) = *(uint2*)lb;
}

// coarse_out[b][c][oh][ow] = cup[p][b*1024 + (oh/2)*32 + ow/2][c] + up_b[c]  (tiled transpose)
__global__ void remap_coarse(const float* __restrict__ up_b) {
    __shared__ float t[64][33];
    int b = blockIdx.z, c0 = blockIdx.y * 32, oh = blockIdx.x;
    int tid = threadIdx.x;
    int poh = (oh & 1) * 2;
    int rbase = b * 1024 + (oh >> 1) * 32;
#pragma unroll
    for (int idx = tid; idx < 64 * 32; idx += 256) {
        int ow = idx >> 5, cc = idx & 31;
        int p = poh + (ow & 1);
        t[ow][cc] = g_cup[((size_t)(p * 8192 + rbase + (ow >> 1))) * 256 + c0 + cc] + up_b[c0 + cc];
    }
    __syncthreads();
#pragma unroll
    for (int idx = tid; idx < 64 * 32; idx += 256) {
        int cc = idx >> 6, ow = idx & 63;
        g_coarse[((size_t)(b * 256 + c0 + cc)) * 4096 + oh * 64 + ow] = t[ow][cc];
    }
}

// gather top-k patch tokens directly from pixel-major g_cup -> split bf16 tokens
__global__ void gather_tokens(const float* __restrict__ up_b) {
    int i = blockIdx.x * 256 + threadIdx.x;
    if (i >= 32768 * 64) return;
    int d = i & 63, row = i >> 6;
    int j = row & 1023, bn = row >> 10, b = bn >> 2, n = bn & 3;
    int k = j >> 2, rr = (j >> 1) & 1, cc = j & 1;
    int pidx = g_topk[bn * 256 + k];
    int c = n * 64 + d;
    float v = g_cup[((size_t)((rr * 2 + cc) * 8192 + b * 1024 + pidx)) * 256 + c] + up_b[c];
    bf16 h, l; split_bf(v, h, l);
    g_t2h[i] = h; g_t2l[i] = l;
}

// y1 = coarse_out + region
__global__ void final_add() {
    int i = blockIdx.x * 256 + threadIdx.x;
    if (i >= 8 * 256 * 4096) return;
    int s = i & 4095, c = (i >> 12) & 255, b = i >> 20;
    int oh = s >> 6, ow = s & 63;
    int p = s >> 2, rr = (s >> 1) & 1, cc = s & 1;
    int sh = 2 * (p >> 5) + rr, sw = 2 * (p & 31) + cc;
    size_t cbase = (size_t)(b * 256 + c) * 4096;
    float v = g_coarse[cbase + oh * 64 + ow] + g_coarse[cbase + sh * 64 + sw];
    int n = c >> 6, d = c & 63, bn = b * 4 + n;
    int k = g_inv[bn * 1024 + p];
    if (k >= 0) v += g_out2[((size_t)bn * 1024 + (k * 4 + rr * 2 + cc)) * 64 + d];
    g_y1[i] = v;
}

// fused: depthwise 3x3 + BN + relu6 + transpose + split -> g_yth/g_ytl [b][s][c]
__global__ void __launch_bounds__(256) dwconv_fused(
    const float* __restrict__ dw_w,
    const float* __restrict__ g1, const float* __restrict__ b1,
    const float* __restrict__ m1, const float* __restrict__ v1)
{
    __shared__ float tile[32 * 193];
    __shared__ float ot[64][33];
    int oh = blockIdx.x, cg = blockIdx.y, b = blockIdx.z;
    int tid = threadIdx.x;
#pragma unroll
    for (int idx = tid; idx < 32 * 192; idx += 256) {
        int c = idx / 192, rw = idx % 192;
        int r = rw >> 6, iw = rw & 63;
        int ih = oh - 1 + r;
        float v = 0.f;
        if ((unsigned)ih < 64u)
            v = g_y1[(((size_t)(b * 256 + cg * 32 + c)) << 12) + ih * 64 + iw];
        tile[c * 193 + rw] = v;
    }
    __syncthreads();
    int c = tid & 31, og = tid >> 5;
    int gc = cg * 32 + c;
    float w[9];
#pragma unroll
    for (int k = 0; k < 9; k++) w[k] = dw_w[gc * 9 + k];
    float sc = g1[gc] / sqrtf(v1[gc] + 1e-5f);
    float off = b1[gc] - m1[gc] * sc;
    bool topEdge = (oh == 0), botEdge = (oh == 63);
    const float* tp = &tile[c * 193];
#pragma unroll
    for (int j = 0; j < 8; j++) {
        int ow = og * 8 + j;
        float acc = 0.f;
#pragma unroll
        for (int kh = 0; kh < 3; kh++) {
            if ((kh == 0 && topEdge) || (kh == 2 && botEdge)) continue;
#pragma unroll
            for (int kw = 0; kw < 3; kw++) {
                int iw = ow + kw - 1;
                if ((unsigned)iw < 64u)
                    acc += w[kh * 3 + kw] * tp[kh * 64 + iw];
            }
        }
        float val = fminf(fmaxf(acc * sc + off, 0.f), 6.f);
        ot[ow][c] = val;
    }
    __syncthreads();
#pragma unroll
    for (int idx = tid; idx < 64 * 32; idx += 256) {
        int ow = idx >> 5, c2 = idx & 31;
        float v = ot[ow][c2];
        bf16 h, l; split_bf(v, h, l);
        size_t o = ((size_t)(b * 4096 + oh * 64 + ow)) * 256 + cg * 32 + c2;
        g_yth[o] = h; g_ytl[o] = l;
    }
}

// ---------------- launch ----------------
extern "C" void kernel_launch(void* const* d_in, const int* in_sizes, int n_in,
                              void* d_out, int out_size) {
    const float* x      = (const float*)d_in[0];
    const float* down_w = (const float*)d_in[1];
    const float* down_b = (const float*)d_in[2];
    const float* up_w   = (const float*)d_in[3];
    const float* up_b   = (const float*)d_in[4];
    const float* cqkv_w = (const float*)d_in[5];
    const float* cqkv_b = (const float*)d_in[6];
    const float* tqkv_w = (const float*)d_in[7];
    const float* tqkv_b = (const float*)d_in[8];
    const float* dw_w   = (const float*)d_in[9];
    const float* bn1_g  = (const float*)d_in[10];
    const float* bn1_b  = (const float*)d_in[11];
    const float* bn1_m  = (const float*)d_in[12];
    const float* bn1_v  = (const float*)d_in[13];
    const float* pw_w   = (const float*)d_in[14];
    const float* bn2_g  = (const float*)d_in[15];
    const float* bn2_b  = (const float*)d_in[16];
    const float* bn2_m  = (const float*)d_in[17];
    const float* bn2_v  = (const float*)d_in[18];
    float* out = (float*)d_out;

    bf16 *c1h, *c1l, *wdh, *wdl, *c2h, *c2l, *wuph, *wupl, *vth, *vtl, *q2h, *q2l;
    bf16 *yth, *ytl, *wph, *wpl, *xdh, *xdl, *t2h, *t2l, *wch, *wcl, *wth, *wtl;
    float *xd, *qkv1, *S1, *S2, *out1, *cup, *qkv2, *out2, *bnsc, *bnoff;
    cudaGetSymbolAddress((void**)&c1h,  g_c1h);
    cudaGetSymbolAddress((void**)&c1l,  g_c1l);
    cudaGetSymbolAddress((void**)&wdh,  g_wdh);
    cudaGetSymbolAddress((void**)&wdl,  g_wdl);
    cudaGetSymbolAddress((void**)&xd,   g_xd);
    cudaGetSymbolAddress((void**)&xdh,  g_xdh);
    cudaGetSymbolAddress((void**)&xdl,  g_xdl);
    cudaGetSymbolAddress((void**)&qkv1, g_qkv1);
    cudaGetSymbolAddress((void**)&S1,   g_S1);
    cudaGetSymbolAddress((void**)&S2,   g_S2);
    cudaGetSymbolAddress((void**)&vth,  g_vth);
    cudaGetSymbolAddress((void**)&vtl,  g_vtl);
    cudaGetSymbolAddress((void**)&q2h,  g_q2h);
    cudaGetSymbolAddress((void**)&q2l,  g_q2l);
    cudaGetSymbolAddress((void**)&out1, g_out1);
    cudaGetSymbolAddress((void**)&c2h,  g_c2h);
    cudaGetSymbolAddress((void**)&c2l,  g_c2l);
    cudaGetSymbolAddress((void**)&wuph, g_wuph);
    cudaGetSymbolAddress((void**)&wupl, g_wupl);
    cudaGetSymbolAddress((void**)&cup,  g_cup);
    cudaGetSymbolAddress((void**)&t2h,  g_t2h);
    cudaGetSymbolAddress((void**)&t2l,  g_t2l);
    cudaGetSymbolAddress((void**)&qkv2, g_qkv2);
    cudaGetSymbolAddress((void**)&out2, g_out2);
    cudaGetSymbolAddress((void**)&yth,  g_yth);
    cudaGetSymbolAddress((void**)&ytl,  g_ytl);
    cudaGetSymbolAddress((void**)&wph,  g_wph);
    cudaGetSymbolAddress((void**)&wpl,  g_wpl);
    cudaGetSymbolAddress((void**)&wch,  g_wch);
    cudaGetSymbolAddress((void**)&wcl,  g_wcl);
    cudaGetSymbolAddress((void**)&wth,  g_wth);
    cudaGetSymbolAddress((void**)&wtl,  g_wtl);
    cudaGetSymbolAddress((void**)&bnsc, g_bnsc);
    cudaGetSymbolAddress((void**)&bnoff, g_bnoff);

    const int FP_SMEM = 2 * 40960 + 4 * 20480 + 4096;   // 167936
    cudaFuncSetAttribute(gemm_mma<128>, cudaFuncAttributeMaxDynamicSharedMemorySize, 81920);
    cudaFuncSetAttribute(gemm_mma<64>,  cudaFuncAttributeMaxDynamicSharedMemorySize, 61440);
    cudaFuncSetAttribute(fused_pv<true>,  cudaFuncAttributeMaxDynamicSharedMemorySize, FP_SMEM);
    cudaFuncSetAttribute(fused_pv<false>, cudaFuncAttributeMaxDynamicSharedMemorySize, FP_SMEM);

    dim3 blk(256);

    // weight prep
    build_wup<<<(4 * 256 * 1024 + 255) / 256, blk>>>(up_w);
    split_wd<<<(256 * 4096 + 255) / 256, blk>>>(down_w);
    splitarr<<<(256 * 256 + 255) / 256, blk>>>(pw_w, wph, wpl, 256 * 256);
    splitarr<<<(192 * 64 + 255) / 256, blk>>>(cqkv_w, wch, wcl, 192 * 64);
    splitarr<<<(192 * 64 + 255) / 256, blk>>>(tqkv_w, wth, wtl, 192 * 64);
    bn_prep<<<1, 256>>>(bn2_g, bn2_b, bn2_m, bn2_v);

    // 1) down conv: smem-tiled im2col(bf16 split) + HMMA GEMM + bias
    im2col1_kernel<<<dim3(32, 8, 8), blk>>>(x);
    gemm_mma<128><<<dim3(2, 64, 1), blk, 81920>>>(c1h, c1l, wdh, wdl, xd, down_b,
        nullptr, nullptr, 4096, 4096, 4096, 256, 1, 0, 0, 0, 0);

    // 2) coarse QKV (HMMA, batched over b,n with head column offset)
    splitarr<<<(8192 * 256 + 255) / 256, blk>>>(xd, xdh, xdl, 8192ll * 256);
    gemm_mma<64><<<dim3(3, 8, 32), blk, 61440>>>(xdh, xdl, wch, wcl, qkv1, cqkv_b,
        nullptr, nullptr, 64, 256, 64, 192, 4, 1024ll * 256, 64, 0, 1024ll * 192);

    // 3) S1 = K @ Q^T (HMMA); stats; fused softmax+colsum+PV; topk
    splitarr<<<(int)((32768ll * 192 + 255) / 256), blk>>>(qkv1, q2h, q2l, 32768ll * 192);
    gemm_mma<128><<<dim3(8, 8, 32), blk, 81920>>>(q2h + 64, q2l + 64, q2h, q2l, S1, nullptr,
        nullptr, nullptr, 64, 192, 192, 1024, 1, 1024ll * 192, 0, 1024ll * 192, 1ll << 20);
    softmax_stats<<<32768, blk>>>(S1);
    vsplit_t<<<dim3(32, 32), blk>>>(qkv1);
    fused_pv<true><<<dim3(8, 32), blk, FP_SMEM>>>(S1, vth, vtl, out1);
    topk_kernel<<<32, 512>>>();

    // 4) up conv (transposed): parity im2col + HMMA GEMM + remap
    im2col2_kernel<<<32768, blk>>>();
    gemm_mma<128><<<dim3(2, 64, 4), blk, 81920>>>(c2h, c2l, wuph, wupl, cup, nullptr,
        nullptr, nullptr, 1024, 1024, 1024, 256, 1, 8192ll * 1024, 0, 256ll * 1024, 8192ll * 256);
    remap_coarse<<<dim3(64, 8, 8), blk>>>(up_b);

    // 5) top-k token gather (split out) + QKV2 (HMMA)
    gather_tokens<<<(32768 * 64 + 255) / 256, blk>>>(up_b);
    gemm_mma<64><<<dim3(3, 256, 1), blk, 61440>>>(t2h, t2l, wth, wtl, qkv2, tqkv_b,
        nullptr, nullptr, 64, 64, 64, 192, 1, 0, 0, 0, 0);

    // 6) S2 (HMMA); stats; fused softmax+PV
    splitarr<<<(int)((32768ll * 192 + 255) / 256), blk>>>(qkv2, q2h, q2l, 32768ll * 192);
    gemm_mma<128><<<dim3(8, 8, 32), blk, 81920>>>(q2h + 64, q2l + 64, q2h, q2l, S2, nullptr,
        nullptr, nullptr, 64, 192, 192, 1024, 1, 1024ll * 192, 0, 1024ll * 192, 1ll << 20);
    softmax_stats<<<32768, blk>>>(S2);
    vsplit_t<<<dim3(32, 32), blk>>>(qkv2);
    fused_pv<false><<<dim3(8, 32), blk, FP_SMEM>>>(S2, vth, vtl, out2);

    // 7) residual + scatter-add; fused dwconv+BN+relu6+transpose+split
    final_add<<<(8 * 256 * 4096 + 255) / 256, blk>>>();
    dwconv_fused<<<dim3(64, 8, 8), blk>>>(dw_w, bn1_g, bn1_b, bn1_m, bn1_v);

    // 8) PW 1x1 conv transposed (A=W, B=Y^T) + fused BN2+relu6, writes d_out directly
    gemm_mma<128><<<dim3(32, 2, 8), blk, 81920>>>(wph, wpl, yth, ytl, out, nullptr,
        bnsc, bnoff, 256, 256, 256, 4096, 1, 0, 0, 4096ll * 256, 256ll * 4096);
}

// round 17
// speedup vs baseline: 1.0529x; 1.0315x over previous
#include <cuda_runtime.h>
#include <cuda_bf16.h>
#include <cstdint>
#include <math.h>

typedef float4 f4;
typedef __nv_bfloat16 bf16;

// ---------------- scratch (device globals; allocation-free rule) ----------------
__device__ bf16  g_c1h[8192ll * 4096];
__device__ bf16  g_c1l[8192ll * 4096];
__device__ bf16  g_wdh[256ll * 4096];
__device__ bf16  g_wdl[256ll * 4096];
__device__ float g_xd  [8192ll * 256];
__device__ bf16  g_xdh [8192ll * 256];
__device__ bf16  g_xdl [8192ll * 256];
__device__ float g_qkv1[32768ll * 192];
__device__ float g_S1  [32ll * 1024 * 1024];
__device__ float g_S2  [32ll * 1024 * 1024];
__device__ bf16  g_vth [32ll * 64 * 1024];
__device__ bf16  g_vtl [32ll * 64 * 1024];
__device__ bf16  g_q2h [32768ll * 192];
__device__ bf16  g_q2l [32768ll * 192];
__device__ float g_stat[32768 * 2];
__device__ float g_statp[32ll * 8 * 1024 * 2];
__device__ float g_scorep[8 * 32 * 1024];
__device__ int   g_topk [32 * 256];
__device__ int   g_inv  [32 * 1024];
__device__ float g_out1[32ll * 1024 * 64];
__device__ bf16  g_c2h[32768ll * 1024];
__device__ bf16  g_c2l[32768ll * 1024];
__device__ bf16  g_wuph[4ll * 256 * 1024];
__device__ bf16  g_wupl[4ll * 256 * 1024];
__device__ float g_cup [32768ll * 256];
__device__ float g_coarse[8ll * 256 * 64 * 64];
__device__ bf16  g_t2h [32768ll * 64];
__device__ bf16  g_t2l [32768ll * 64];
__device__ float g_qkv2[32768ll * 192];
__device__ float g_out2[32ll * 1024 * 64];
__device__ float g_y1  [8ll * 256 * 64 * 64];
__device__ bf16  g_yth [8ll * 4096 * 256];
__device__ bf16  g_ytl [8ll * 4096 * 256];
__device__ bf16  g_wph [256 * 256];
__device__ bf16  g_wpl [256 * 256];
__device__ bf16  g_wch [192 * 64];
__device__ bf16  g_wcl [192 * 64];
__device__ bf16  g_wth [192 * 64];
__device__ bf16  g_wtl [192 * 64];
__device__ float g_bnsc[256];
__device__ float g_bnoff[256];

// =================== helpers ===================
__device__ __forceinline__ uint32_t smem_u32(const void* p) {
    uint32_t a;
    asm("{ .reg .u64 t; cvta.to.shared.u64 t, %1; cvt.u32.u64 %0, t; }" : "=r"(a) : "l"(p));
    return a;
}
__device__ __forceinline__ void cpasync16(uint32_t s, const void* g) {
    asm volatile("cp.async.cg.shared.global [%0], [%1], 16;" :: "r"(s), "l"(g) : "memory");
}
__device__ __forceinline__ void ldsm4(uint32_t* r, uint32_t addr) {
    asm volatile("ldmatrix.sync.aligned.m8n8.x4.shared.b16 {%0,%1,%2,%3}, [%4];"
                 : "=r"(r[0]), "=r"(r[1]), "=r"(r[2]), "=r"(r[3]) : "r"(addr));
}
__device__ __forceinline__ void sts64(uint32_t addr, uint32_t a, uint32_t b) {
    asm volatile("st.shared.v2.b32 [%0], {%1, %2};" :: "r"(addr), "r"(a), "r"(b) : "memory");
}
#define CP_COMMIT() asm volatile("cp.async.commit_group;" ::: "memory")
#define CP_WAIT1()  asm volatile("cp.async.wait_group 1;" ::: "memory")
#define CP_WAIT0()  asm volatile("cp.async.wait_group 0;" ::: "memory")

#define MMA16816(d, a, b) \
    asm volatile("mma.sync.aligned.m16n8k16.row.col.f32.bf16.bf16.f32 " \
        "{%0,%1,%2,%3}, {%4,%5,%6,%7}, {%8,%9}, {%0,%1,%2,%3};" \
        : "+f"((d)[0]), "+f"((d)[1]), "+f"((d)[2]), "+f"((d)[3]) \
        : "r"((a)[0]), "r"((a)[1]), "r"((a)[2]), "r"((a)[3]), \
          "r"((b)[0]), "r"((b)[1]))

// ---------------- bf16 split helpers ----------------
__device__ __forceinline__ void split_bf(float v, bf16& h, bf16& l) {
    h = __float2bfloat16(v);
    l = __float2bfloat16(v - __bfloat162float(h));
}
__device__ __forceinline__ uint32_t pack2(bf16 a, bf16 b) {
    return ((uint32_t)__bfloat16_as_ushort(b) << 16) | __bfloat16_as_ushort(a);
}

// ========= split-bf16 3-term HMMA GEMM: C = (Ah+Al)(Bh+Bl)^T (approx) =========
// STATS: also emit per-(row, 128-col block) softmax partials (m, z) to g_statp.
template<int BN, bool STATS = false>
__global__ void __launch_bounds__(256, 1) gemm_mma(
    const bf16* __restrict__ Ah, const bf16* __restrict__ Al,
    const bf16* __restrict__ Bh, const bf16* __restrict__ Bl,
    float* __restrict__ C, const float* __restrict__ bias,
    const float* __restrict__ rsc, const float* __restrict__ roff,
    int K, int lda, int ldb, int ldc,
    int aDiv, long long aHi, long long aLo, long long bStr, long long cStr)
{
    constexpr int WM = (BN == 128) ? 4 : 2;
    constexpr int RS = 80;
    constexpr int ASZ = 128 * RS;
    constexpr int BSZ = BN * RS;
    constexpr int STG = 2 * ASZ + 2 * BSZ;

    extern __shared__ char smraw[];
    uint32_t sb = smem_u32(smraw);

    const int tid = threadIdx.x;
    const int wid = tid >> 5, lane = tid & 31;
    long long bz = blockIdx.z;
    long long aOff = (bz / aDiv) * aHi + (bz % aDiv) * aLo;
    Ah += aOff; Al += aOff;
    Bh += bz * bStr; Bl += bz * bStr;
    C += bz * cStr;
    const int m0 = blockIdx.y * 128, n0 = blockIdx.x * BN;

    const int wm0 = (BN == 128) ? (wid & 1) * 64 : (wid & 3) * 32;
    const int wn0 = (BN == 128) ? (wid >> 1) * 32 : (wid >> 2) * 32;

    float acc[WM][4][4];
#pragma unroll
    for (int i = 0; i < WM; i++)
#pragma unroll
        for (int j = 0; j < 4; j++)
#pragma unroll
            for (int k = 0; k < 4; k++) acc[i][j][k] = 0.f;

    const int T = K >> 5;

    auto fill = [&](int t) {
        int k0 = t << 5;
        uint32_t st = sb + (t & 1) * STG;
#pragma unroll
        for (int half = 0; half < 2; half++) {
            int idx = tid + half * 256;
            int r = idx >> 2, q = idx & 3;
            long long go = (long long)(m0 + r) * lda + k0 + q * 8;
            uint32_t sA = st + r * RS + q * 16;
            cpasync16(sA, Ah + go);
            cpasync16(sA + ASZ, Al + go);
        }
#pragma unroll
        for (int half = 0; half < BN / 64; half++) {
            int idx = tid + half * 256;
            int r = idx >> 2, q = idx & 3;
            long long go = (long long)(n0 + r) * ldb + k0 + q * 8;
            uint32_t sB = st + 2 * ASZ + r * RS + q * 16;
            cpasync16(sB, Bh + go);
            cpasync16(sB + BSZ, Bl + go);
        }
    };

    fill(0); CP_COMMIT();
    fill(1); CP_COMMIT();

    const uint32_t aPat = (((lane >> 3) & 1) * 8 + (lane & 7)) * RS + (lane >> 4) * 16;
    const uint32_t bPat = (((lane >> 4) & 1) * 8 + (lane & 7)) * RS + ((lane >> 3) & 1) * 16;

    for (int t = 0; t < T; t++) {
        CP_WAIT1();
        __syncthreads();
        uint32_t st = sb + (t & 1) * STG;
#pragma unroll
        for (int ks = 0; ks < 2; ks++) {
            uint32_t ah[WM][4], alr[WM][4];
            uint32_t aoff = st + wm0 * RS + ks * 32 + aPat;
#pragma unroll
            for (int mt = 0; mt < WM; mt++) {
                ldsm4(ah[mt],  aoff + mt * 16 * RS);
                ldsm4(alr[mt], aoff + mt * 16 * RS + ASZ);
            }
            uint32_t bh[4][2], blr[4][2];
            uint32_t boff = st + 2 * ASZ + wn0 * RS + ks * 32 + bPat;
            {
                uint32_t tb[4];
                ldsm4(tb, boff);
                bh[0][0] = tb[0]; bh[0][1] = tb[1]; bh[1][0] = tb[2]; bh[1][1] = tb[3];
                ldsm4(tb, boff + 16 * RS);
                bh[2][0] = tb[0]; bh[2][1] = tb[1]; bh[3][0] = tb[2]; bh[3][1] = tb[3];
                ldsm4(tb, boff + BSZ);
                blr[0][0] = tb[0]; blr[0][1] = tb[1]; blr[1][0] = tb[2]; blr[1][1] = tb[3];
                ldsm4(tb, boff + BSZ + 16 * RS);
                blr[2][0] = tb[0]; blr[2][1] = tb[1]; blr[3][0] = tb[2]; blr[3][1] = tb[3];
            }
#pragma unroll
            for (int term = 0; term < 3; term++)
#pragma unroll
                for (int mt = 0; mt < WM; mt++)
#pragma unroll
                    for (int nt = 0; nt < 4; nt++)
                        MMA16816(acc[mt][nt],
                                 (term == 2) ? alr[mt] : ah[mt],
                                 (term == 1) ? blr[nt] : bh[nt]);
        }
        __syncthreads();
        if (t + 2 < T) fill(t + 2);
        CP_COMMIT();
    }

#pragma unroll
    for (int mt = 0; mt < WM; mt++) {
        int r = wm0 + mt * 16 + (lane >> 2);
        float s0 = 1.f, o0 = 0.f, s1 = 1.f, o1 = 0.f;
        bool rowaff = (rsc != nullptr);
        if (rowaff) {
            s0 = rsc[m0 + r]; o0 = roff[m0 + r];
            s1 = rsc[m0 + r + 8]; o1 = roff[m0 + r + 8];
        }
#pragma unroll
        for (int nt = 0; nt < 4; nt++) {
            int c = wn0 + nt * 8 + (lane & 3) * 2;
            float b0 = 0.f, b1 = 0.f;
            if (bias) { b0 = bias[n0 + c]; b1 = bias[n0 + c + 1]; }
            float2 v0, v1;
            if (rowaff) {
                v0.x = fminf(fmaxf(acc[mt][nt][0] * s0 + o0, 0.f), 6.f);
                v0.y = fminf(fmaxf(acc[mt][nt][1] * s0 + o0, 0.f), 6.f);
                v1.x = fminf(fmaxf(acc[mt][nt][2] * s1 + o1, 0.f), 6.f);
                v1.y = fminf(fmaxf(acc[mt][nt][3] * s1 + o1, 0.f), 6.f);
            } else {
                v0.x = acc[mt][nt][0] + b0; v0.y = acc[mt][nt][1] + b1;
                v1.x = acc[mt][nt][2] + b0; v1.y = acc[mt][nt][3] + b1;
            }
            *(float2*)(C + (long long)(m0 + r) * ldc + n0 + c) = v0;
            *(float2*)(C + (long long)(m0 + r + 8) * ldc + n0 + c) = v1;
        }
    }

    if (STATS) {
        // per-(row, this 128-col block) (max, expsum) partials.
        // Reuse the (now dead) tile buffer at smraw+0 for the 4KB scratch.
        __syncthreads();
        float* sst = (float*)smraw;   // [128 rows][4 warp-cols][2] = 4096 B
#pragma unroll
        for (int mt = 0; mt < WM; mt++) {
            float mA = -1e30f, mB = -1e30f;
#pragma unroll
            for (int nt = 0; nt < 4; nt++) {
                mA = fmaxf(mA, fmaxf(acc[mt][nt][0], acc[mt][nt][1]));
                mB = fmaxf(mB, fmaxf(acc[mt][nt][2], acc[mt][nt][3]));
            }
            float zA = 0.f, zB = 0.f;
#pragma unroll
            for (int nt = 0; nt < 4; nt++) {
                zA += expf(acc[mt][nt][0] - mA) + expf(acc[mt][nt][1] - mA);
                zB += expf(acc[mt][nt][2] - mB) + expf(acc[mt][nt][3] - mB);
            }
#pragma unroll
            for (int o = 1; o < 4; o <<= 1) {
                float mo = __shfl_xor_sync(0xffffffffu, mA, o);
                float zo = __shfl_xor_sync(0xffffffffu, zA, o);
                float nm = fmaxf(mA, mo);
                zA = zA * expf(mA - nm) + zo * expf(mo - nm); mA = nm;
                mo = __shfl_xor_sync(0xffffffffu, mB, o);
                zo = __shfl_xor_sync(0xffffffffu, zB, o);
                nm = fmaxf(mB, mo);
                zB = zB * expf(mB - nm) + zo * expf(mo - nm); mB = nm;
            }
            if ((lane & 3) == 0) {
                int rA = wm0 + mt * 16 + (lane >> 2);
                int wc = wn0 >> 5;
                sst[(rA * 4 + wc) * 2] = mA; sst[(rA * 4 + wc) * 2 + 1] = zA;
                sst[((rA + 8) * 4 + wc) * 2] = mB; sst[((rA + 8) * 4 + wc) * 2 + 1] = zB;
            }
        }
        __syncthreads();
        if (tid < 128) {
            float m = -1e30f;
#pragma unroll
            for (int w = 0; w < 4; w++) m = fmaxf(m, sst[(tid * 4 + w) * 2]);
            float z = 0.f;
#pragma unroll
            for (int w = 0; w < 4; w++) z += sst[(tid * 4 + w) * 2 + 1] * expf(sst[(tid * 4 + w) * 2] - m);
            size_t o = ((size_t)(bz * 8 + blockIdx.x) * 1024 + m0 + tid) * 2;
            g_statp[o] = m; g_statp[o + 1] = z;
        }
    }
}

// combine 8 j-block partials per row -> g_stat (m, 1/Z)
__global__ void stats_combine() {
    int row = blockIdx.x * 256 + threadIdx.x;   // 0..32767 (bn*1024 + r)
    int bn = row >> 10, r = row & 1023;
    float m = -1e30f;
#pragma unroll
    for (int jb = 0; jb < 8; jb++)
        m = fmaxf(m, g_statp[(((size_t)bn * 8 + jb) * 1024 + r) * 2]);
    float z = 0.f;
#pragma unroll
    for (int jb = 0; jb < 8; jb++) {
        size_t idx = (((size_t)bn * 8 + jb) * 1024 + r) * 2;
        z += g_statp[idx + 1] * expf(g_statp[idx] - m);
    }
    g_stat[row * 2] = m;
    g_stat[row * 2 + 1] = 1.0f / z;
}

// ========= fused softmax + colsum(reg) + P@V (probs never touch HBM) =========
template<bool COLSUM>
__global__ void __launch_bounds__(256, 1) fused_pv(
    const float* __restrict__ S, const bf16* __restrict__ Vth, const bf16* __restrict__ Vtl,
    float* __restrict__ outp)
{
    constexpr int RS = 80;
    constexpr int PSUB = 128 * RS;
    constexpr int PSZ = 4 * PSUB;
    constexpr int VSUB = 64 * RS;
    constexpr int VSZ = 4 * VSUB;
    extern __shared__ char smraw[];
    uint32_t sb = smem_u32(smraw);
    uint32_t Ph = sb, Pl = sb + PSZ;
    uint32_t Vb = sb + 2 * PSZ;
    float* csred = (float*)(smraw + 2 * PSZ + 4 * VSZ);

    const int tid = threadIdx.x, wid = tid >> 5, lane = tid & 31;
    const int bn = blockIdx.y, i0 = blockIdx.x * 128;
    S   += ((size_t)bn << 20) + (size_t)i0 * 1024;
    Vth += (size_t)bn * 65536;
    Vtl += (size_t)bn * 65536;
    outp += ((size_t)bn * 1024 + i0) * 64;
    const float* st2 = g_stat + ((size_t)(bn * 1024 + i0)) * 2;

    auto loadV = [&](int jc) {
        uint32_t vh = Vb + (jc & 1) * (2 * VSZ);
        uint32_t vl = vh + VSZ;
#pragma unroll
        for (int q = 0; q < 4; q++) {
            int idx = tid + q * 256;
            int sc = idx >> 8, rem = idx & 255;
            int d = rem >> 2, seg = rem & 3;
            size_t src = (size_t)d * 1024 + jc * 128 + sc * 32 + seg * 8;
            uint32_t dst = sc * VSUB + d * RS + seg * 16;
            cpasync16(vh + dst, Vth + src);
            cpasync16(vl + dst, Vtl + src);
        }
    };

    float acc[8][4];
#pragma unroll
    for (int i = 0; i < 8; i++)
#pragma unroll
        for (int j = 0; j < 4; j++) acc[i][j] = 0.f;

    const uint32_t aPat = (((lane >> 3) & 1) * 8 + (lane & 7)) * RS + (lane >> 4) * 16;
    const uint32_t bPat = (((lane >> 4) & 1) * 8 + (lane & 7)) * RS + ((lane >> 3) & 1) * 16;
    const int psc = lane >> 3, ppos = lane & 7;

    loadV(0); CP_COMMIT();

    for (int jc = 0; jc < 8; jc++) {
        float cs0 = 0.f, cs1 = 0.f, cs2 = 0.f, cs3 = 0.f;
#pragma unroll
        for (int rr = 0; rr < 16; rr++) {
            int row = wid * 16 + rr;
            float m = st2[row * 2], iz = st2[row * 2 + 1];
            f4 v = *(const f4*)(S + (size_t)row * 1024 + jc * 128 + lane * 4);
            float p0 = expf(v.x - m) * iz;
            float p1 = expf(v.y - m) * iz;
            float p2 = expf(v.z - m) * iz;
            float p3 = expf(v.w - m) * iz;
            if (COLSUM) { cs0 += p0; cs1 += p1; cs2 += p2; cs3 += p3; }
            bf16 h0, l0, h1, l1, h2, l2, h3, l3;
            split_bf(p0, h0, l0); split_bf(p1, h1, l1);
            split_bf(p2, h2, l2); split_bf(p3, h3, l3);
            uint32_t off = psc * PSUB + row * RS + ppos * 8;
            sts64(Ph + off, pack2(h0, h1), pack2(h2, h3));
            sts64(Pl + off, pack2(l0, l1), pack2(l2, l3));
        }
        if (COLSUM) {
            f4 c4; c4.x = cs0; c4.y = cs1; c4.z = cs2; c4.w = cs3;
            *(f4*)(csred + wid * 128 + lane * 4) = c4;
        }
        CP_WAIT0();
        __syncthreads();
        if (COLSUM && tid < 128) {
            float s = 0.f;
#pragma unroll
            for (int w = 0; w < 8; w++) s += csred[w * 128 + tid];
            g_scorep[((size_t)blockIdx.x * 32 + bn) * 1024 + jc * 128 + tid] = s;
        }
        if (jc + 1 < 8) { loadV(jc + 1); CP_COMMIT(); }
        uint32_t vh = Vb + (jc & 1) * (2 * VSZ), vl = vh + VSZ;
#pragma unroll
        for (int ks = 0; ks < 8; ks++) {
            uint32_t pbase = Ph + (ks >> 1) * PSUB + (ks & 1) * 32 + wid * 16 * RS + aPat;
            uint32_t ah[4], al[4];
            ldsm4(ah, pbase);
            ldsm4(al, pbase + PSZ);
            uint32_t vbase = (ks >> 1) * VSUB + (ks & 1) * 32;
            uint32_t bh[8][2], bl[8][2];
#pragma unroll
            for (int n2 = 0; n2 < 4; n2++) {
                uint32_t tb[4];
                ldsm4(tb, vh + vbase + n2 * 16 * RS + bPat);
                bh[2 * n2][0] = tb[0]; bh[2 * n2][1] = tb[1];
                bh[2 * n2 + 1][0] = tb[2]; bh[2 * n2 + 1][1] = tb[3];
                ldsm4(tb, vl + vbase + n2 * 16 * RS + bPat);
                bl[2 * n2][0] = tb[0]; bl[2 * n2][1] = tb[1];
                bl[2 * n2 + 1][0] = tb[2]; bl[2 * n2 + 1][1] = tb[3];
            }
#pragma unroll
            for (int term = 0; term < 3; term++)
#pragma unroll
                for (int nt = 0; nt < 8; nt++)
                    MMA16816(acc[nt],
                             (term == 2) ? al : ah,
                             (term == 1) ? bl[nt] : bh[nt]);
        }
        __syncthreads();
    }

    int r = wid * 16 + (lane >> 2);
#pragma unroll
    for (int nt = 0; nt < 8; nt++) {
        int c = nt * 8 + (lane & 3) * 2;
        float2 v0; v0.x = acc[nt][0]; v0.y = acc[nt][1];
        float2 v1; v1.x = acc[nt][2]; v1.y = acc[nt][3];
        *(float2*)(outp + (size_t)r * 64 + c) = v0;
        *(float2*)(outp + (size_t)(r + 8) * 64 + c) = v1;
    }
}

// im2col for down conv (4x4, stride2, pad1), smem-tiled.
__global__ void __launch_bounds__(256) im2col1_kernel(const float* __restrict__ x) {
    __shared__ float tile[32 * 257];
    int oh = blockIdx.x, cg = blockIdx.y, b = blockIdx.z;
    int tid = threadIdx.x;
#pragma unroll
    for (int idx = tid; idx < 32 * 256; idx += 256) {
        int ic = idx >> 8, rw = idx & 255;
        int r = rw >> 6, iw = rw & 63;
        int ih = 2 * oh - 1 + r;
        float v = 0.f;
        if ((unsigned)ih < 64u)
            v = x[(((long long)(b * 256 + cg * 32 + ic)) << 12) + ih * 64 + iw];
        tile[ic * 257 + rw] = v;
    }
    __syncthreads();
    int ow = tid >> 3, sub = tid & 7;
    int iw0 = 2 * ow - 1;
    long long orow = ((long long)(b * 1024 + oh * 32 + ow)) * 4096 + (cg * 32 + sub * 4) * 16;
#pragma unroll
    for (int j = 0; j < 4; j++) {
        const float* tp = &tile[(sub * 4 + j) * 257];
        bf16 hb[16], lb[16];
#pragma unroll
        for (int kh = 0; kh < 4; kh++) {
#pragma unroll
            for (int kw = 0; kw < 4; kw++) {
                int iw = iw0 + kw;
                float v = ((unsigned)iw < 64u) ? tp[kh * 64 + iw] : 0.f;
                split_bf(v, hb[kh * 4 + kw], lb[kh * 4 + kw]);
            }
        }
        *(uint4*)(g_c1h + orow + j * 16) = *(uint4*)hb;
        *(uint4*)(g_c1h + orow + j * 16 + 8) = *(uint4*)(hb + 8);
        *(uint4*)(g_c1l + orow + j * 16) = *(uint4*)lb;
        *(uint4*)(g_c1l + orow + j * 16 + 8) = *(uint4*)(lb + 8);
    }
}

// split down_w [256 x 4096]
__global__ void split_wd(const float* __restrict__ w) {
    int i = blockIdx.x * 256 + threadIdx.x;
    if (i >= 256 * 4096) return;
    bf16 h, l; split_bf(w[i], h, l);
    g_wdh[i] = h; g_wdl[i] = l;
}

// generic fp32 -> split bf16
__global__ void splitarr(const float* __restrict__ src, bf16* __restrict__ h,
                         bf16* __restrict__ l, long long n) {
    long long i = (long long)blockIdx.x * 256 + threadIdx.x;
    if (i >= n) return;
    bf16 hh, ll; split_bf(src[i], hh, ll);
    h[i] = hh; l[i] = ll;
}

// BN2 constants
__global__ void bn_prep(const float* __restrict__ g2, const float* __restrict__ b2,
                        const float* __restrict__ m2, const float* __restrict__ v2) {
    int i = threadIdx.x;
    float sc = g2[i] / sqrtf(v2[i] + 1e-5f);
    g_bnsc[i] = sc;
    g_bnoff[i] = b2[i] - m2[i] * sc;
}

// V^T split (tiled transpose): vth[bn][d][tok] = split(qkv[bn*1024+tok][128+d])
__global__ void vsplit_t(const float* __restrict__ qkv) {
    __shared__ float t[32][65];
    int bn = blockIdx.y, tk0 = blockIdx.x * 32;
    int tid = threadIdx.x;
#pragma unroll
    for (int idx = tid; idx < 32 * 64; idx += 256) {
        int tok = idx >> 6, d = idx & 63;
        t[tok][d] = qkv[((size_t)bn * 1024 + tk0 + tok) * 192 + 128 + d];
    }
    __syncthreads();
#pragma unroll
    for (int idx = tid; idx < 32 * 64; idx += 256) {
        int d = idx >> 5, tok = idx & 31;
        bf16 h, l; split_bf(t[tok][d], h, l);
        size_t o = ((size_t)bn * 64 + d) * 1024 + tk0 + tok;
        g_vth[o] = h; g_vtl[o] = l;
    }
}

// bitonic full sort of 1024 (score,idx) pairs descending (jax tie-break: lower idx first)
__global__ void __launch_bounds__(512) topk_kernel() {
    int bn = blockIdx.x, tid = threadIdx.x;
    __shared__ float sv[1024];
    __shared__ int   si[1024];
    for (int i = tid; i < 1024; i += 512) {
        float s = 0.f;
#pragma unroll
        for (int ic = 0; ic < 8; ic++) s += g_scorep[((size_t)ic * 32 + bn) * 1024 + i];
        sv[i] = s; si[i] = i;
    }
    __syncthreads();
    for (int k = 2; k <= 1024; k <<= 1) {
        for (int j = k >> 1; j > 0; j >>= 1) {
            for (int i = tid; i < 1024; i += 512) {
                int ixj = i ^ j;
                if (ixj > i) {
                    float va = sv[i], vb = sv[ixj];
                    int ia = si[i], ib = si[ixj];
                    bool aFirst = (va > vb) || (va == vb && ia < ib);
                    bool descSeg = ((i & k) == 0);
                    if (descSeg ? !aFirst : aFirst) { sv[i] = vb; sv[ixj] = va; si[i] = ib; si[ixj] = ia; }
                }
            }
            __syncthreads();
        }
    }
    for (int i = tid; i < 1024; i += 512) g_inv[bn * 1024 + i] = -1;
    __syncthreads();
    for (int kk = tid; kk < 256; kk += 512) {
        int id = si[kk];
        g_topk[bn * 256 + kk] = id;
        g_inv[bn * 1024 + id] = kk;
    }
}

// permuted up-conv weights (bf16 hi/lo): wup[p][cout][cin*4+t]
__global__ void build_wup(const float* __restrict__ up_w) {
    int i = blockIdx.x * 256 + threadIdx.x;
    if (i >= 4 * 256 * 1024) return;
    int t = i & 3, cin = (i >> 2) & 255, cout = (i >> 10) & 255, p = i >> 18;
    int kh = (1 - (p >> 1)) + 2 * (t >> 1);
    int kw = (1 - (p & 1)) + 2 * (t & 1);
    float v = up_w[(((long long)cin * 256 + cout) * 4 + kh) * 4 + kw];
    bf16 h, l; split_bf(v, h, l);
    g_wuph[i] = h; g_wupl[i] = l;
}

// im2col for conv-transpose: thread per (row, cin) -> 4 contiguous elems
__global__ void im2col2_kernel() {
    int i = blockIdx.x * 256 + threadIdx.x;
    if (i >= 32768 * 256) return;
    int cin = i & 255, row = i >> 8;
    int n = cin >> 6, d = cin & 63;
    int p = row >> 13, r = row & 8191;
    int b = r >> 10, q = r & 1023, qh = q >> 5, qw = q & 31;
    int oh = qh * 2 + (p >> 1), ow = qw * 2 + (p & 1);
    bf16 hb[4], lb[4];
#pragma unroll
    for (int t = 0; t < 4; t++) {
        int dh = t >> 1, dw = t & 1;
        int ih = ((oh + 1) >> 1) - dh, iw = ((ow + 1) >> 1) - dw;
        float v = 0.f;
        if ((unsigned)ih < 32u && (unsigned)iw < 32u)
            v = g_out1[((size_t)(b * 4 + n) * 1024 + ih * 32 + iw) * 64 + d];
        split_bf(v, hb[t], lb[t]);
    }
    long long o = (long long)row * 1024 + cin * 4;
    *(uint2*)(g_c2h + o) = *(uint2*)hb;
    *(uint2*)(g_c2l + o) = *(uint2*)lb;
}

// coarse_out[b][c][oh][ow] = cup[p][b*1024 + (oh/2)*32 + ow/2][c] + up_b[c]  (tiled transpose)
__global__ void remap_coarse(const float* __restrict__ up_b) {
    __shared__ float t[64][33];
    int b = blockIdx.z, c0 = blockIdx.y * 32, oh = blockIdx.x;
    int tid = threadIdx.x;
    int poh = (oh & 1) * 2;
    int rbase = b * 1024 + (oh >> 1) * 32;
#pragma unroll
    for (int idx = tid; idx < 64 * 32; idx += 256) {
        int ow = idx >> 5, cc = idx & 31;
        int p = poh + (ow & 1);
        t[ow][cc] = g_cup[((size_t)(p * 8192 + rbase + (ow >> 1))) * 256 + c0 + cc] + up_b[c0 + cc];
    }
    __syncthreads();
#pragma unroll
    for (int idx = tid; idx < 64 * 32; idx += 256) {
        int cc = idx >> 6, ow = idx & 63;
        g_coarse[((size_t)(b * 256 + c0 + cc)) * 4096 + oh * 64 + ow] = t[ow][cc];
    }
}

// gather top-k patch tokens directly from pixel-major g_cup -> split bf16 tokens
__global__ void gather_tokens(const float* __restrict__ up_b) {
    int i = blockIdx.x * 256 + threadIdx.x;
    if (i >= 32768 * 64) return;
    int d = i & 63, row = i >> 6;
    int j = row & 1023, bn = row >> 10, b = bn >> 2, n = bn & 3;
    int k = j >> 2, rr = (j >> 1) & 1, cc = j & 1;
    int pidx = g_topk[bn * 256 + k];
    int c = n * 64 + d;
    float v = g_cup[((size_t)((rr * 2 + cc) * 8192 + b * 1024 + pidx)) * 256 + c] + up_b[c];
    bf16 h, l; split_bf(v, h, l);
    g_t2h[i] = h; g_t2l[i] = l;
}

// y1 = coarse_out + region
__global__ void final_add() {
    int i = blockIdx.x * 256 + threadIdx.x;
    if (i >= 8 * 256 * 4096) return;
    int s = i & 4095, c = (i >> 12) & 255, b = i >> 20;
    int oh = s >> 6, ow = s & 63;
    int p = s >> 2, rr = (s >> 1) & 1, cc = s & 1;
    int sh = 2 * (p >> 5) + rr, sw = 2 * (p & 31) + cc;
    size_t cbase = (size_t)(b * 256 + c) * 4096;
    float v = g_coarse[cbase + oh * 64 + ow] + g_coarse[cbase + sh * 64 + sw];
    int n = c >> 6, d = c & 63, bn = b * 4 + n;
    int k = g_inv[bn * 1024 + p];
    if (k >= 0) v += g_out2[((size_t)bn * 1024 + (k * 4 + rr * 2 + cc)) * 64 + d];
    g_y1[i] = v;
}

// fused: depthwise 3x3 + BN + relu6 + transpose + split -> g_yth/g_ytl [b][s][c]
__global__ void __launch_bounds__(256) dwconv_fused(
    const float* __restrict__ dw_w,
    const float* __restrict__ g1, const float* __restrict__ b1,
    const float* __restrict__ m1, const float* __restrict__ v1)
{
    __shared__ float tile[32 * 193];
    __shared__ float ot[64][33];
    int oh = blockIdx.x, cg = blockIdx.y, b = blockIdx.z;
    int tid = threadIdx.x;
#pragma unroll
    for (int idx = tid; idx < 32 * 192; idx += 256) {
        int c = idx / 192, rw = idx % 192;
        int r = rw >> 6, iw = rw & 63;
        int ih = oh - 1 + r;
        float v = 0.f;
        if ((unsigned)ih < 64u)
            v = g_y1[(((size_t)(b * 256 + cg * 32 + c)) << 12) + ih * 64 + iw];
        tile[c * 193 + rw] = v;
    }
    __syncthreads();
    int c = tid & 31, og = tid >> 5;
    int gc = cg * 32 + c;
    float w[9];
#pragma unroll
    for (int k = 0; k < 9; k++) w[k] = dw_w[gc * 9 + k];
    float sc = g1[gc] / sqrtf(v1[gc] + 1e-5f);
    float off = b1[gc] - m1[gc] * sc;
    bool topEdge = (oh == 0), botEdge = (oh == 63);
    const float* tp = &tile[c * 193];
#pragma unroll
    for (int j = 0; j < 8; j++) {
        int ow = og * 8 + j;
        float acc = 0.f;
#pragma unroll
        for (int kh = 0; kh < 3; kh++) {
            if ((kh == 0 && topEdge) || (kh == 2 && botEdge)) continue;
#pragma unroll
            for (int kw = 0; kw < 3; kw++) {
                int iw = ow + kw - 1;
                if ((unsigned)iw < 64u)
                    acc += w[kh * 3 + kw] * tp[kh * 64 + iw];
            }
        }
        float val = fminf(fmaxf(acc * sc + off, 0.f), 6.f);
        ot[ow][c] = val;
    }
    __syncthreads();
#pragma unroll
    for (int idx = tid; idx < 64 * 32; idx += 256) {
        int ow = idx >> 5, c2 = idx & 31;
        float v = ot[ow][c2];
        bf16 h, l; split_bf(v, h, l);
        size_t o = ((size_t)(b * 4096 + oh * 64 + ow)) * 256 + cg * 32 + c2;
        g_yth[o] = h; g_ytl[o] = l;
    }
}

// ---------------- launch ----------------
extern "C" void kernel_launch(void* const* d_in, const int* in_sizes, int n_in,
                              void* d_out, int out_size) {
    const float* x      = (const float*)d_in[0];
    const float* down_w = (const float*)d_in[1];
    const float* down_b = (const float*)d_in[2];
    const float* up_w   = (const float*)d_in[3];
    const float* up_b   = (const float*)d_in[4];
    const float* cqkv_w = (const float*)d_in[5];
    const float* cqkv_b = (const float*)d_in[6];
    const float* tqkv_w = (const float*)d_in[7];
    const float* tqkv_b = (const float*)d_in[8];
    const float* dw_w   = (const float*)d_in[9];
    const float* bn1_g  = (const float*)d_in[10];
    const float* bn1_b  = (const float*)d_in[11];
    const float* bn1_m  = (const float*)d_in[12];
    const float* bn1_v  = (const float*)d_in[13];
    const float* pw_w   = (const float*)d_in[14];
    const float* bn2_g  = (const float*)d_in[15];
    const float* bn2_b  = (const float*)d_in[16];
    const float* bn2_m  = (const float*)d_in[17];
    const float* bn2_v  = (const float*)d_in[18];
    float* out = (float*)d_out;

    bf16 *c1h, *c1l, *wdh, *wdl, *c2h, *c2l, *wuph, *wupl, *vth, *vtl, *q2h, *q2l;
    bf16 *yth, *ytl, *wph, *wpl, *xdh, *xdl, *t2h, *t2l, *wch, *wcl, *wth, *wtl;
    float *xd, *qkv1, *S1, *S2, *out1, *cup, *qkv2, *out2, *bnsc, *bnoff;
    cudaGetSymbolAddress((void**)&c1h,  g_c1h);
    cudaGetSymbolAddress((void**)&c1l,  g_c1l);
    cudaGetSymbolAddress((void**)&wdh,  g_wdh);
    cudaGetSymbolAddress((void**)&wdl,  g_wdl);
    cudaGetSymbolAddress((void**)&xd,   g_xd);
    cudaGetSymbolAddress((void**)&xdh,  g_xdh);
    cudaGetSymbolAddress((void**)&xdl,  g_xdl);
    cudaGetSymbolAddress((void**)&qkv1, g_qkv1);
    cudaGetSymbolAddress((void**)&S1,   g_S1);
    cudaGetSymbolAddress((void**)&S2,   g_S2);
    cudaGetSymbolAddress((void**)&vth,  g_vth);
    cudaGetSymbolAddress((void**)&vtl,  g_vtl);
    cudaGetSymbolAddress((void**)&q2h,  g_q2h);
    cudaGetSymbolAddress((void**)&q2l,  g_q2l);
    cudaGetSymbolAddress((void**)&out1, g_out1);
    cudaGetSymbolAddress((void**)&c2h,  g_c2h);
    cudaGetSymbolAddress((void**)&c2l,  g_c2l);
    cudaGetSymbolAddress((void**)&wuph, g_wuph);
    cudaGetSymbolAddress((void**)&wupl, g_wupl);
    cudaGetSymbolAddress((void**)&cup,  g_cup);
    cudaGetSymbolAddress((void**)&t2h,  g_t2h);
    cudaGetSymbolAddress((void**)&t2l,  g_t2l);
    cudaGetSymbolAddress((void**)&qkv2, g_qkv2);
    cudaGetSymbolAddress((void**)&out2, g_out2);
    cudaGetSymbolAddress((void**)&yth,  g_yth);
    cudaGetSymbolAddress((void**)&ytl,  g_ytl);
    cudaGetSymbolAddress((void**)&wph,  g_wph);
    cudaGetSymbolAddress((void**)&wpl,  g_wpl);
    cudaGetSymbolAddress((void**)&wch,  g_wch);
    cudaGetSymbolAddress((void**)&wcl,  g_wcl);
    cudaGetSymbolAddress((void**)&wth,  g_wth);
    cudaGetSymbolAddress((void**)&wtl,  g_wtl);
    cudaGetSymbolAddress((void**)&bnsc, g_bnsc);
    cudaGetSymbolAddress((void**)&bnoff, g_bnoff);

    const int FP_SMEM = 2 * 40960 + 4 * 20480 + 4096;   // 167936
    cudaFuncSetAttribute(gemm_mma<128, false>, cudaFuncAttributeMaxDynamicSharedMemorySize, 81920);
    cudaFuncSetAttribute(gemm_mma<128, true>,  cudaFuncAttributeMaxDynamicSharedMemorySize, 81920);
    cudaFuncSetAttribute(gemm_mma<64, false>,  cudaFuncAttributeMaxDynamicSharedMemorySize, 61440);
    cudaFuncSetAttribute(fused_pv<true>,  cudaFuncAttributeMaxDynamicSharedMemorySize, FP_SMEM);
    cudaFuncSetAttribute(fused_pv<false>, cudaFuncAttributeMaxDynamicSharedMemorySize, FP_SMEM);

    dim3 blk(256);

    // weight prep
    build_wup<<<(4 * 256 * 1024 + 255) / 256, blk>>>(up_w);
    split_wd<<<(256 * 4096 + 255) / 256, blk>>>(down_w);
    splitarr<<<(256 * 256 + 255) / 256, blk>>>(pw_w, wph, wpl, 256 * 256);
    splitarr<<<(192 * 64 + 255) / 256, blk>>>(cqkv_w, wch, wcl, 192 * 64);
    splitarr<<<(192 * 64 + 255) / 256, blk>>>(tqkv_w, wth, wtl, 192 * 64);
    bn_prep<<<1, 256>>>(bn2_g, bn2_b, bn2_m, bn2_v);

    // 1) down conv: smem-tiled im2col(bf16 split) + HMMA GEMM + bias
    im2col1_kernel<<<dim3(32, 8, 8), blk>>>(x);
    gemm_mma<128><<<dim3(2, 64, 1), blk, 81920>>>(c1h, c1l, wdh, wdl, xd, down_b,
        nullptr, nullptr, 4096, 4096, 4096, 256, 1, 0, 0, 0, 0);

    // 2) coarse QKV (HMMA, batched over b,n with head column offset)
    splitarr<<<(8192 * 256 + 255) / 256, blk>>>(xd, xdh, xdl, 8192ll * 256);
    gemm_mma<64><<<dim3(3, 8, 32), blk, 61440>>>(xdh, xdl, wch, wcl, qkv1, cqkv_b,
        nullptr, nullptr, 64, 256, 64, 192, 4, 1024ll * 256, 64, 0, 1024ll * 192);

    // 3) S1 = K @ Q^T (HMMA + fused stats partials); combine; fused softmax+colsum+PV; topk
    splitarr<<<(int)((32768ll * 192 + 255) / 256), blk>>>(qkv1, q2h, q2l, 32768ll * 192);
    gemm_mma<128, true><<<dim3(8, 8, 32), blk, 81920>>>(q2h + 64, q2l + 64, q2h, q2l, S1, nullptr,
        nullptr, nullptr, 64, 192, 192, 1024, 1, 1024ll * 192, 0, 1024ll * 192, 1ll << 20);
    stats_combine<<<128, blk>>>();
    vsplit_t<<<dim3(32, 32), blk>>>(qkv1);
    fused_pv<true><<<dim3(8, 32), blk, FP_SMEM>>>(S1, vth, vtl, out1);
    topk_kernel<<<32, 512>>>();

    // 4) up conv (transposed): parity im2col + HMMA GEMM + remap
    im2col2_kernel<<<32768, blk>>>();
    gemm_mma<128><<<dim3(2, 64, 4), blk, 81920>>>(c2h, c2l, wuph, wupl, cup, nullptr,
        nullptr, nullptr, 1024, 1024, 1024, 256, 1, 8192ll * 1024, 0, 256ll * 1024, 8192ll * 256);
    remap_coarse<<<dim3(64, 8, 8), blk>>>(up_b);

    // 5) top-k token gather (split out) + QKV2 (HMMA)
    gather_tokens<<<(32768 * 64 + 255) / 256, blk>>>(up_b);
    gemm_mma<64><<<dim3(3, 256, 1), blk, 61440>>>(t2h, t2l, wth, wtl, qkv2, tqkv_b,
        nullptr, nullptr, 64, 64, 64, 192, 1, 0, 0, 0, 0);

    // 6) S2 (HMMA + fused stats partials); combine; fused softmax+PV
    splitarr<<<(int)((32768ll * 192 + 255) / 256), blk>>>(qkv2, q2h, q2l, 32768ll * 192);
    gemm_mma<128, true><<<dim3(8, 8, 32), blk, 81920>>>(q2h + 64, q2l + 64, q2h, q2l, S2, nullptr,
        nullptr, nullptr, 64, 192, 192, 1024, 1, 1024ll * 192, 0, 1024ll * 192, 1ll << 20);
    stats_combine<<<128, blk>>>();
    vsplit_t<<<dim3(32, 32), blk>>>(qkv2);
    fused_pv<false><<<dim3(8, 32), blk, FP_SMEM>>>(S2, vth, vtl, out2);

    // 7) residual + scatter-add; fused dwconv+BN+relu6+transpose+split
    final_add<<<(8 * 256 * 4096 + 255) / 256, blk>>>();
    dwconv_fused<<<dim3(64, 8, 8), blk>>>(dw_w, bn1_g, bn1_b, bn1_m, bn1_v);

    // 8) PW 1x1 conv transposed (A=W, B=Y^T) + fused BN2+relu6, writes d_out directly
    gemm_mma<128><<<dim3(32, 2, 8), blk, 81920>>>(wph, wpl, yth, ytl, out, nullptr,
        bnsc, bnoff, 256, 256, 256, 4096, 1, 0, 0, 4096ll * 256, 256ll * 4096);
}